// round 1
// baseline (speedup 1.0000x reference)
#include <cuda_runtime.h>
#include <cuda_bf16.h>
#include <math.h>

#define B_      128
#define G_      2048
#define M_      64
#define T_      128
#define HID_    32
#define KSPLIT  4

// ---------------- scratch (device globals; no allocation) ----------------
__device__ float g_C[B_ * M_ * M_];              // data cov per batch (once)
__device__ float g_covp[KSPLIT * B_ * M_ * M_];  // partial cov accumulators
__device__ float g_S[B_ * M_ * M_];              // Sigma^{-1}
__device__ float g_Tmp[B_ * M_ * M_];            // Sinv @ C
__device__ float g_M[B_ * M_ * M_];              // Sinv C Sinv
__device__ float g_T1[B_ * G_];
__device__ float g_T2[B_ * G_];
__device__ float g_g[B_ * G_];                   // current gamma

// ---------------- init gamma = 1 ----------------
__global__ void k_init() {
    int i = blockIdx.x * blockDim.x + threadIdx.x;
    if (i < B_ * G_) g_g[i] = 1.0f;
}

// ---------------- C_b = data_b data_b^T / T  (once) ----------------
__global__ void k_datacov(const float* __restrict__ data) {
    __shared__ float sh[M_][T_ + 1];  // 64 x 129 floats
    int b = blockIdx.x;
    const float* d = data + (size_t)b * M_ * T_;
    for (int i = threadIdx.x; i < M_ * T_; i += blockDim.x)
        sh[i >> 7][i & 127] = d[i];
    __syncthreads();
    for (int idx = threadIdx.x; idx < M_ * M_; idx += blockDim.x) {
        int m = idx >> 6, n = idx & 63;
        float acc = 0.f;
        #pragma unroll 8
        for (int t = 0; t < T_; t++) acc += sh[m][t] * sh[n][t];
        g_C[(size_t)b * 4096 + idx] = acc * (1.0f / (float)T_);
    }
}

// ---------------- cov partial: covp[ks][b] = sum_{k in slice} g[b,k] a_k a_k^T ----------------
__global__ void k_cov(const float* __restrict__ A) {
    __shared__ float shA[M_][33];
    __shared__ float shg[32];
    int b = blockIdx.x;
    int ks = blockIdx.y;
    int tid = threadIdx.x;
    int tx = tid & 15, ty = tid >> 4;
    float acc[4][4] = {};
    int kbeg = ks * (G_ / KSPLIT), kend = kbeg + (G_ / KSPLIT);
    for (int k0 = kbeg; k0 < kend; k0 += 32) {
        for (int i = tid; i < M_ * 32; i += 256) {
            int r = i >> 5, c = i & 31;
            shA[r][c] = A[(size_t)r * G_ + k0 + c];
        }
        if (tid < 32) shg[tid] = g_g[(size_t)b * G_ + k0 + tid];
        __syncthreads();
        #pragma unroll 4
        for (int k = 0; k < 32; k++) {
            float gv = shg[k];
            float am[4], an[4];
            #pragma unroll
            for (int i = 0; i < 4; i++) am[i] = shA[ty * 4 + i][k] * gv;
            #pragma unroll
            for (int j = 0; j < 4; j++) an[j] = shA[tx * 4 + j][k];
            #pragma unroll
            for (int i = 0; i < 4; i++)
                #pragma unroll
                for (int j = 0; j < 4; j++) acc[i][j] += am[i] * an[j];
        }
        __syncthreads();
    }
    float* dst = g_covp + ((size_t)ks * B_ + b) * 4096;
    #pragma unroll
    for (int i = 0; i < 4; i++)
        #pragma unroll
        for (int j = 0; j < 4; j++)
            dst[(ty * 4 + i) * 64 + tx * 4 + j] = acc[i][j];
}

// ---------------- Gauss-Jordan inverse with partial pivoting (64x64 per batch) ----------------
__global__ void k_inv() {
    __shared__ float aug[M_][130];
    __shared__ int s_piv;
    int b = blockIdx.x, tid = threadIdx.x;
    // load: sum K-split partials + 0.1 I on the left, identity on the right
    for (int i = tid; i < M_ * M_; i += 256) {
        int r = i >> 6, c = i & 63;
        float v = g_covp[(size_t)0 * B_ * 4096 + (size_t)b * 4096 + i]
                + g_covp[(size_t)1 * B_ * 4096 + (size_t)b * 4096 + i]
                + g_covp[(size_t)2 * B_ * 4096 + (size_t)b * 4096 + i]
                + g_covp[(size_t)3 * B_ * 4096 + (size_t)b * 4096 + i];
        if (r == c) v += 0.1f;
        aug[r][c] = v;
        aug[r][64 + c] = (r == c) ? 1.0f : 0.0f;
    }
    __syncthreads();
    for (int k = 0; k < M_; k++) {
        // pivot search (warp 0)
        if (tid < 32) {
            float best = -1.0f; int bi = k;
            for (int i = k + tid; i < M_; i += 32) {
                float v = fabsf(aug[i][k]);
                if (v > best) { best = v; bi = i; }
            }
            #pragma unroll
            for (int o = 16; o > 0; o >>= 1) {
                float ob = __shfl_down_sync(0xffffffffu, best, o);
                int   oi = __shfl_down_sync(0xffffffffu, bi, o);
                if (ob > best) { best = ob; bi = oi; }
            }
            if (tid == 0) s_piv = bi;
        }
        __syncthreads();
        int p = s_piv;
        float pv = aug[p][k];
        float vk = 0.f, vp = 0.f;
        if (tid < 128) { vk = aug[k][tid]; vp = aug[p][tid]; }
        __syncthreads();
        if (tid < 128) {
            aug[k][tid] = vp / pv;            // row k := normalized pivot row
            if (p != k) aug[p][tid] = vk;     // swap
        }
        __syncthreads();
        // elimination: cols j != k, rows i != k
        {
            int j = tid & 127;
            int half = tid >> 7;
            if (j != k) {
                float rk = aug[k][j];
                int i0 = half * 32;
                #pragma unroll 8
                for (int ii = 0; ii < 32; ii++) {
                    int i = i0 + ii;
                    if (i != k) aug[i][j] -= aug[i][k] * rk;
                }
            }
        }
        __syncthreads();
    }
    for (int i = tid; i < M_ * M_; i += 256) {
        int r = i >> 6, c = i & 63;
        g_S[(size_t)b * 4096 + i] = aug[r][64 + c];
    }
}

// ---------------- 64x64x64 batched GEMM: mode 0: Tmp = S@C ; mode 1: M = Tmp@S ----------------
__global__ void k_mm64(int mode) {
    __shared__ float sx[M_][65];
    __shared__ float sy[M_][65];
    int b = blockIdx.x, tid = threadIdx.x;
    const float* X = (mode == 0 ? g_S : g_Tmp) + (size_t)b * 4096;
    const float* Y = (mode == 0 ? g_C : g_S) + (size_t)b * 4096;
    float* O = (mode == 0 ? g_Tmp : g_M) + (size_t)b * 4096;
    for (int i = tid; i < 4096; i += 256) {
        sx[i >> 6][i & 63] = X[i];
        sy[i >> 6][i & 63] = Y[i];
    }
    __syncthreads();
    int tx = tid & 15, ty = tid >> 4;
    float acc[4][4] = {};
    #pragma unroll 4
    for (int k = 0; k < M_; k++) {
        float xm[4], yn[4];
        #pragma unroll
        for (int i = 0; i < 4; i++) xm[i] = sx[ty * 4 + i][k];
        #pragma unroll
        for (int j = 0; j < 4; j++) yn[j] = sy[k][tx * 4 + j];
        #pragma unroll
        for (int i = 0; i < 4; i++)
            #pragma unroll
            for (int j = 0; j < 4; j++) acc[i][j] += xm[i] * yn[j];
    }
    #pragma unroll
    for (int i = 0; i < 4; i++)
        #pragma unroll
        for (int j = 0; j < 4; j++)
            O[(ty * 4 + i) * 64 + tx * 4 + j] = acc[i][j];
}

// ---------------- quadratic forms: T1 = a^T M a, T2 = |a^T S a| ----------------
__global__ void k_quad(const float* __restrict__ A) {
    __shared__ float mat[M_][65];
    __shared__ float ach[M_][65];
    __shared__ float red[16][68];
    int gc = blockIdx.x;   // 32 chunks of 64 gridpoints
    int b  = blockIdx.y;
    int tid = threadIdx.x;
    int tx = tid & 15, ty = tid >> 4;
    int g0 = gc * 64;
    for (int i = tid; i < 4096; i += 256) {
        int r = i >> 6, c = i & 63;
        ach[r][c] = A[(size_t)r * G_ + g0 + c];
    }
    for (int ph = 0; ph < 2; ph++) {
        const float* src = (ph == 0 ? g_M : g_S) + (size_t)b * 4096;
        for (int i = tid; i < 4096; i += 256)
            mat[i >> 6][i & 63] = src[i];
        __syncthreads();
        float acc[4][4] = {};
        #pragma unroll 4
        for (int k = 0; k < M_; k++) {
            float am[4], ag[4];
            #pragma unroll
            for (int i = 0; i < 4; i++) am[i] = mat[ty * 4 + i][k];
            #pragma unroll
            for (int j = 0; j < 4; j++) ag[j] = ach[k][tx * 4 + j];
            #pragma unroll
            for (int i = 0; i < 4; i++)
                #pragma unroll
                for (int j = 0; j < 4; j++) acc[i][j] += am[i] * ag[j];
        }
        // epilogue: partial column dot  sum_m A[m,g] * V[m,g]
        float p[4] = {};
        #pragma unroll
        for (int i = 0; i < 4; i++)
            #pragma unroll
            for (int j = 0; j < 4; j++)
                p[j] += ach[ty * 4 + i][tx * 4 + j] * acc[i][j];
        #pragma unroll
        for (int j = 0; j < 4; j++) red[ty][tx * 4 + j] = p[j];
        __syncthreads();
        if (tid < 64) {
            float s = 0.f;
            #pragma unroll
            for (int t = 0; t < 16; t++) s += red[t][tid];
            if (ph == 0) g_T1[(size_t)b * G_ + g0 + tid] = s;
            else         g_T2[(size_t)b * G_ + g0 + tid] = fabsf(s);
        }
        __syncthreads();
    }
}

// ---------------- per-gridpoint MLP: x=[T1,T2,g] -> 32 -> 32 -> 1 ----------------
__global__ void k_mlp(const float* __restrict__ W1, const float* __restrict__ B1,
                      const float* __restrict__ W2, const float* __restrict__ B2,
                      const float* __restrict__ W3, const float* __restrict__ B3,
                      int it, int last, float* __restrict__ out) {
    int g = blockIdx.x;
    int b = threadIdx.x;
    __shared__ float sW1[96], sB1[32], sW2[1024], sB2[32], sW3[32], sB3;
    size_t gidx = (size_t)it * G_ + g;
    const float* w1 = W1 + gidx * 96;
    const float* w2 = W2 + gidx * 1024;
    if (b < 96) sW1[b] = w1[b];
    if (b < 32) {
        sB1[b] = B1[gidx * 32 + b];
        sB2[b] = B2[gidx * 32 + b];
        sW3[b] = W3[gidx * 32 + b];
    }
    if (b == 0) sB3 = B3[gidx];
    for (int i = b; i < 1024; i += 128) sW2[i] = w2[i];
    __syncthreads();

    float x0 = g_T1[(size_t)b * G_ + g];
    float x1 = g_T2[(size_t)b * G_ + g];
    float x2 = g_g[(size_t)b * G_ + g];

    float h[HID_];
    #pragma unroll
    for (int j = 0; j < HID_; j++) {
        float v = x0 * sW1[j] + x1 * sW1[32 + j] + x2 * sW1[64 + j] + sB1[j];
        h[j] = fmaxf(v, 0.0f);
    }
    float h2[HID_];
    #pragma unroll
    for (int j = 0; j < HID_; j++) h2[j] = sB2[j];
    #pragma unroll
    for (int j = 0; j < HID_; j++) {
        float hv = h[j];
        #pragma unroll
        for (int k = 0; k < HID_; k++) h2[k] += hv * sW2[j * 32 + k];
    }
    float o = sB3;
    #pragma unroll
    for (int k = 0; k < HID_; k++) o += fmaxf(h2[k], 0.0f) * sW3[k];

    if (last) out[(size_t)b * G_ + g] = o;
    else      g_g[(size_t)b * G_ + g] = o;
}

// ---------------- launch ----------------
extern "C" void kernel_launch(void* const* d_in, const int* in_sizes, int n_in,
                              void* d_out, int out_size) {
    const float* data = (const float*)d_in[0];
    const float* A    = (const float*)d_in[1];
    const float* W1   = (const float*)d_in[2];
    const float* b1   = (const float*)d_in[3];
    const float* W2   = (const float*)d_in[4];
    const float* b2   = (const float*)d_in[5];
    const float* W3   = (const float*)d_in[6];
    const float* b3   = (const float*)d_in[7];
    float* out = (float*)d_out;

    k_init<<<(B_ * G_ + 255) / 256, 256>>>();
    k_datacov<<<B_, 256>>>(data);
    for (int it = 0; it < 3; it++) {
        k_cov<<<dim3(B_, KSPLIT), 256>>>(A);
        k_inv<<<B_, 256>>>();
        k_mm64<<<B_, 256>>>(0);
        k_mm64<<<B_, 256>>>(1);
        k_quad<<<dim3(G_ / 64, B_), 256>>>(A);
        k_mlp<<<G_, 128>>>(W1, b1, W2, b2, W3, b3, it, it == 2 ? 1 : 0, out);
    }
}

// round 3
// speedup vs baseline: 1.0437x; 1.0437x over previous
#include <cuda_runtime.h>
#include <cuda_bf16.h>
#include <cstdint>
#include <math.h>

#define B_      128
#define G_      2048
#define M_      64
#define T_      128
#define HID_    32
#define KSPLIT  4

// ================= scratch (device globals) =================
__device__ float g_C[B_ * M_ * M_];
__device__ float g_covp[KSPLIT * B_ * M_ * M_];
__device__ float g_S[B_ * M_ * M_];
__device__ float g_Tmp[B_ * M_ * M_];
__device__ float g_T1[B_ * G_];
__device__ float g_T2[B_ * G_];
__device__ float g_g[B_ * G_];
// stacked W per batch: rows 0..63 = M = S C S, rows 64..127 = S; bf16 2-term split
__device__ __nv_bfloat16 g_Whi[B_ * 128 * 64];
__device__ __nv_bfloat16 g_Wlo[B_ * 128 * 64];

// ---------------- init gamma = 1 ----------------
__global__ void k_init() {
    int i = blockIdx.x * blockDim.x + threadIdx.x;
    if (i < B_ * G_) g_g[i] = 1.0f;
}

// ---------------- C_b = data_b data_b^T / T (once) ----------------
__global__ void k_datacov(const float* __restrict__ data) {
    __shared__ float sh[M_][T_ + 1];
    int b = blockIdx.x;
    const float* d = data + (size_t)b * M_ * T_;
    for (int i = threadIdx.x; i < M_ * T_; i += blockDim.x)
        sh[i >> 7][i & 127] = d[i];
    __syncthreads();
    for (int idx = threadIdx.x; idx < M_ * M_; idx += blockDim.x) {
        int m = idx >> 6, n = idx & 63;
        float acc = 0.f;
        #pragma unroll 8
        for (int t = 0; t < T_; t++) acc += sh[m][t] * sh[n][t];
        g_C[(size_t)b * 4096 + idx] = acc * (1.0f / (float)T_);
    }
}

// ---------------- cov partial: covp[ks][b] = sum_{k in slice} g[b,k] a_k a_k^T ----------------
__global__ void k_cov(const float* __restrict__ A) {
    __shared__ float shA[M_][33];
    __shared__ float shg[32];
    int b = blockIdx.x;
    int ks = blockIdx.y;
    int tid = threadIdx.x;
    int tx = tid & 15, ty = tid >> 4;
    float acc[4][4] = {};
    int kbeg = ks * (G_ / KSPLIT), kend = kbeg + (G_ / KSPLIT);
    for (int k0 = kbeg; k0 < kend; k0 += 32) {
        for (int i = tid; i < M_ * 32; i += 256) {
            int r = i >> 5, c = i & 31;
            shA[r][c] = A[(size_t)r * G_ + k0 + c];
        }
        if (tid < 32) shg[tid] = g_g[(size_t)b * G_ + k0 + tid];
        __syncthreads();
        #pragma unroll 4
        for (int k = 0; k < 32; k++) {
            float gv = shg[k];
            float am[4], an[4];
            #pragma unroll
            for (int i = 0; i < 4; i++) am[i] = shA[ty * 4 + i][k] * gv;
            #pragma unroll
            for (int j = 0; j < 4; j++) an[j] = shA[tx * 4 + j][k];
            #pragma unroll
            for (int i = 0; i < 4; i++)
                #pragma unroll
                for (int j = 0; j < 4; j++) acc[i][j] += am[i] * an[j];
        }
        __syncthreads();
    }
    float* dst = g_covp + ((size_t)ks * B_ + b) * 4096;
    #pragma unroll
    for (int i = 0; i < 4; i++)
        #pragma unroll
        for (int j = 0; j < 4; j++)
            dst[(ty * 4 + i) * 64 + tx * 4 + j] = acc[i][j];
}

// ---------------- Gauss-Jordan inverse, implicit pivoting, 2 barriers/step ----------------
__global__ void __launch_bounds__(128) k_inv() {
    __shared__ float aug[M_][130];
    __shared__ float fcol[M_];
    __shared__ int s_p;
    __shared__ float s_pv;
    __shared__ int pivk[M_];
    __shared__ int used[M_];
    int b = blockIdx.x, tid = threadIdx.x;

    for (int i = tid; i < M_ * M_; i += 128) {
        int r = i >> 6, c = i & 63;
        float v = g_covp[(size_t)b * 4096 + i]
                + g_covp[(size_t)(B_ + b) * 4096 + i]
                + g_covp[(size_t)(2 * B_ + b) * 4096 + i]
                + g_covp[(size_t)(3 * B_ + b) * 4096 + i];
        if (r == c) v += 0.1f;
        aug[r][c] = v;
        aug[r][64 + c] = (r == c) ? 1.0f : 0.0f;
    }
    if (tid < M_) used[tid] = 0;
    __syncthreads();

    for (int k = 0; k < M_; k++) {
        if (tid < 32) {
            float best = -1.0f; int bi = 0;
            #pragma unroll
            for (int s = 0; s < 2; s++) {
                int i = s * 32 + tid;
                float v = used[i] ? -2.0f : fabsf(aug[i][k]);
                if (v > best) { best = v; bi = i; }
            }
            #pragma unroll
            for (int o = 16; o > 0; o >>= 1) {
                float ob = __shfl_down_sync(0xffffffffu, best, o);
                int   oi = __shfl_down_sync(0xffffffffu, bi, o);
                if (ob > best) { best = ob; bi = oi; }
            }
            if (tid == 0) { s_p = bi; s_pv = aug[bi][k]; }
        } else if (tid < 96) {
            fcol[tid - 32] = aug[tid - 32][k];
        }
        __syncthreads();
        int p = s_p;
        float rn = aug[p][tid] * (1.0f / s_pv);
        #pragma unroll 8
        for (int i = 0; i < M_; i++) {
            aug[i][tid] = aug[i][tid] - fcol[i] * rn;
        }
        aug[p][tid] = rn;
        if (tid == 0) { used[p] = 1; pivk[k] = p; }
        __syncthreads();
    }

    for (int i = tid; i < M_ * M_; i += 128) {
        int k = i >> 6, c = i & 63;
        float v = aug[pivk[k]][64 + c];
        g_S[(size_t)b * 4096 + i] = v;
        __nv_bfloat16 h = __float2bfloat16(v);
        g_Whi[(size_t)b * 8192 + (size_t)(64 + k) * 64 + c] = h;
        g_Wlo[(size_t)b * 8192 + (size_t)(64 + k) * 64 + c] =
            __float2bfloat16(v - __bfloat162float(h));
    }
}

// ---------------- 64x64x64 batched GEMM: mode 0: Tmp = S@C ; mode 1: W rows 0..63 = Tmp@S ----------------
__global__ void k_mm64(int mode) {
    __shared__ float sx[M_][65];
    __shared__ float sy[M_][65];
    int b = blockIdx.x, tid = threadIdx.x;
    const float* X = (mode == 0 ? g_S : g_Tmp) + (size_t)b * 4096;
    const float* Y = (mode == 0 ? g_C : g_S) + (size_t)b * 4096;
    for (int i = tid; i < 4096; i += 256) {
        sx[i >> 6][i & 63] = X[i];
        sy[i >> 6][i & 63] = Y[i];
    }
    __syncthreads();
    int tx = tid & 15, ty = tid >> 4;
    float acc[4][4] = {};
    #pragma unroll 4
    for (int k = 0; k < M_; k++) {
        float xm[4], yn[4];
        #pragma unroll
        for (int i = 0; i < 4; i++) xm[i] = sx[ty * 4 + i][k];
        #pragma unroll
        for (int j = 0; j < 4; j++) yn[j] = sy[k][tx * 4 + j];
        #pragma unroll
        for (int i = 0; i < 4; i++)
            #pragma unroll
            for (int j = 0; j < 4; j++) acc[i][j] += xm[i] * yn[j];
    }
    if (mode == 0) {
        float* O = g_Tmp + (size_t)b * 4096;
        #pragma unroll
        for (int i = 0; i < 4; i++)
            #pragma unroll
            for (int j = 0; j < 4; j++)
                O[(ty * 4 + i) * 64 + tx * 4 + j] = acc[i][j];
    } else {
        #pragma unroll
        for (int i = 0; i < 4; i++)
            #pragma unroll
            for (int j = 0; j < 4; j++) {
                int r = ty * 4 + i, c = tx * 4 + j;
                float v = acc[i][j];
                __nv_bfloat16 h = __float2bfloat16(v);
                g_Whi[(size_t)b * 8192 + (size_t)r * 64 + c] = h;
                g_Wlo[(size_t)b * 8192 + (size_t)r * 64 + c] =
                    __float2bfloat16(v - __bfloat162float(h));
            }
    }
}

// ---------------- quadratic forms via mma.sync bf16 split ----------------
// Block: batch b, 64 grid cols. 8 warps, warp w owns W rows 16w..16w+15.
// V[128,64] = W[128,64] @ Bchunk[64,64]; T1[g] = sum_m A[m,g]V[m,g] (rows 0..63),
// T2[g] = |sum_m A[m,g]V[64+m,g]| (rows 64..127).
#define QLD 72   // smem row stride in bf16 elems (144B, 16B-aligned)
#define QOFF_WHI   0
#define QOFF_WLO   (QOFF_WHI + 128 * QLD * 2)
#define QOFF_BHI   (QOFF_WLO + 128 * QLD * 2)
#define QOFF_BLO   (QOFF_BHI + 64 * QLD * 2)
#define QOFF_SPART (QOFF_BLO + 64 * QLD * 2)
#define QSMEM_TOTAL (QOFF_SPART + 8 * 64 * 4)

__device__ __forceinline__ void mma16816(float d[4], const uint32_t a[4], const uint32_t b[2]) {
    asm volatile(
        "mma.sync.aligned.m16n8k16.row.col.f32.bf16.bf16.f32 "
        "{%0,%1,%2,%3}, {%4,%5,%6,%7}, {%8,%9}, {%0,%1,%2,%3};"
        : "+f"(d[0]), "+f"(d[1]), "+f"(d[2]), "+f"(d[3])
        : "r"(a[0]), "r"(a[1]), "r"(a[2]), "r"(a[3]), "r"(b[0]), "r"(b[1]));
}

__global__ void __launch_bounds__(256) k_quad_mma(const float* __restrict__ A) {
    extern __shared__ char smem[];
    __nv_bfloat16* sWhi = (__nv_bfloat16*)(smem + QOFF_WHI);
    __nv_bfloat16* sWlo = (__nv_bfloat16*)(smem + QOFF_WLO);
    __nv_bfloat16* sBhi = (__nv_bfloat16*)(smem + QOFF_BHI);
    __nv_bfloat16* sBlo = (__nv_bfloat16*)(smem + QOFF_BLO);
    float* spart = (float*)(smem + QOFF_SPART);

    int tid = threadIdx.x;
    int wid = tid >> 5, lane = tid & 31;
    int g0 = blockIdx.x * 64;
    int b  = blockIdx.y;

    // load W hi/lo (row-major 128x64 bf16) in 16B chunks into padded smem
    {
        const uint4* srcH = (const uint4*)(g_Whi + (size_t)b * 8192);
        const uint4* srcL = (const uint4*)(g_Wlo + (size_t)b * 8192);
        for (int i = tid; i < 1024; i += 256) {      // 128 rows x 8 chunks
            int r = i >> 3, c = i & 7;
            *(uint4*)&sWhi[r * QLD + c * 8] = srcH[i];
            *(uint4*)&sWlo[r * QLD + c * 8] = srcL[i];
        }
    }
    // load A chunk (64 k-rows x 64 g-cols), transpose to sB[g][k], bf16 split
    for (int i = tid; i < 4096; i += 256) {
        int k = i >> 6, g = i & 63;
        float x = A[(size_t)k * G_ + g0 + g];
        __nv_bfloat16 h = __float2bfloat16(x);
        sBhi[g * QLD + k] = h;
        sBlo[g * QLD + k] = __float2bfloat16(x - __bfloat162float(h));
    }
    __syncthreads();

    int wrow = wid * 16;
    int r0 = wrow + (lane >> 2);
    int cq = (lane & 3) * 2;

    float d[8][4];
    #pragma unroll
    for (int t = 0; t < 8; t++)
        #pragma unroll
        for (int j = 0; j < 4; j++) d[t][j] = 0.0f;

    #pragma unroll
    for (int sp = 0; sp < 3; sp++) {
        const __nv_bfloat16* Wsrc = (sp == 2) ? sWlo : sWhi;
        const __nv_bfloat16* Bsrc = (sp == 1) ? sBlo : sBhi;
        #pragma unroll
        for (int ks = 0; ks < 4; ks++) {
            int kb = ks * 16;
            uint32_t a[4];
            a[0] = *(const uint32_t*)&Wsrc[r0 * QLD + kb + cq];
            a[1] = *(const uint32_t*)&Wsrc[(r0 + 8) * QLD + kb + cq];
            a[2] = *(const uint32_t*)&Wsrc[r0 * QLD + kb + cq + 8];
            a[3] = *(const uint32_t*)&Wsrc[(r0 + 8) * QLD + kb + cq + 8];
            int n = lane >> 2;
            #pragma unroll
            for (int t = 0; t < 8; t++) {
                uint32_t bb[2];
                bb[0] = *(const uint32_t*)&Bsrc[(t * 8 + n) * QLD + kb + cq];
                bb[1] = *(const uint32_t*)&Bsrc[(t * 8 + n) * QLD + kb + cq + 8];
                mma16816(d[t], a, bb);
            }
        }
    }

    // epilogue: p[col] = sum over this warp's 16 rows of A[m,g]*V[m,g]
    int mbase = wrow & 63;
    int m0 = mbase + (lane >> 2);
    #pragma unroll
    for (int t = 0; t < 8; t++) {
        int g = t * 8 + cq;
        float a00 = __bfloat162float(sBhi[g * QLD + m0])       + __bfloat162float(sBlo[g * QLD + m0]);
        float a10 = __bfloat162float(sBhi[g * QLD + m0 + 8])   + __bfloat162float(sBlo[g * QLD + m0 + 8]);
        float a01 = __bfloat162float(sBhi[(g + 1) * QLD + m0]) + __bfloat162float(sBlo[(g + 1) * QLD + m0]);
        float a11 = __bfloat162float(sBhi[(g + 1) * QLD + m0 + 8]) + __bfloat162float(sBlo[(g + 1) * QLD + m0 + 8]);
        float p0 = d[t][0] * a00 + d[t][2] * a10;
        float p1 = d[t][1] * a01 + d[t][3] * a11;
        #pragma unroll
        for (int o = 4; o < 32; o <<= 1) {
            p0 += __shfl_xor_sync(0xffffffffu, p0, o);
            p1 += __shfl_xor_sync(0xffffffffu, p1, o);
        }
        if (lane < 4) {
            spart[wid * 64 + g] = p0;
            spart[wid * 64 + g + 1] = p1;
        }
    }
    __syncthreads();
    if (tid < 64) {
        int g = tid;
        float t1 = spart[g] + spart[64 + g] + spart[128 + g] + spart[192 + g];
        float t2 = spart[256 + g] + spart[320 + g] + spart[384 + g] + spart[448 + g];
        g_T1[(size_t)b * G_ + g0 + g] = t1;
        g_T2[(size_t)b * G_ + g0 + g] = fabsf(t2);
    }
}

// ---------------- per-gridpoint MLP ----------------
__global__ void k_mlp(const float* __restrict__ W1, const float* __restrict__ B1,
                      const float* __restrict__ W2, const float* __restrict__ B2,
                      const float* __restrict__ W3, const float* __restrict__ B3,
                      int it, int last, float* __restrict__ out) {
    int g = blockIdx.x;
    int b = threadIdx.x;
    __shared__ float sW1[96], sB1[32], sW2[1024], sB2[32], sW3[32], sB3;
    size_t gidx = (size_t)it * G_ + g;
    const float* w1 = W1 + gidx * 96;
    const float* w2 = W2 + gidx * 1024;
    if (b < 96) sW1[b] = w1[b];
    if (b < 32) {
        sB1[b] = B1[gidx * 32 + b];
        sB2[b] = B2[gidx * 32 + b];
        sW3[b] = W3[gidx * 32 + b];
    }
    if (b == 0) sB3 = B3[gidx];
    for (int i = b; i < 1024; i += 128) sW2[i] = w2[i];
    __syncthreads();

    float x0 = g_T1[(size_t)b * G_ + g];
    float x1 = g_T2[(size_t)b * G_ + g];
    float x2 = g_g[(size_t)b * G_ + g];

    float h[HID_];
    #pragma unroll
    for (int j = 0; j < HID_; j++) {
        float v = x0 * sW1[j] + x1 * sW1[32 + j] + x2 * sW1[64 + j] + sB1[j];
        h[j] = fmaxf(v, 0.0f);
    }
    float h2[HID_];
    #pragma unroll
    for (int j = 0; j < HID_; j++) h2[j] = sB2[j];
    #pragma unroll
    for (int j = 0; j < HID_; j++) {
        float hv = h[j];
        #pragma unroll
        for (int k = 0; k < HID_; k++) h2[k] += hv * sW2[j * 32 + k];
    }
    float o = sB3;
    #pragma unroll
    for (int k = 0; k < HID_; k++) o += fmaxf(h2[k], 0.0f) * sW3[k];

    if (last) out[(size_t)b * G_ + g] = o;
    else      g_g[(size_t)b * G_ + g] = o;
}

// ---------------- launch ----------------
extern "C" void kernel_launch(void* const* d_in, const int* in_sizes, int n_in,
                              void* d_out, int out_size) {
    const float* data = (const float*)d_in[0];
    const float* A    = (const float*)d_in[1];
    const float* W1   = (const float*)d_in[2];
    const float* b1   = (const float*)d_in[3];
    const float* W2   = (const float*)d_in[4];
    const float* b2   = (const float*)d_in[5];
    const float* W3   = (const float*)d_in[6];
    const float* b3   = (const float*)d_in[7];
    float* out = (float*)d_out;

    static int smem_set = 0;
    if (!smem_set) {
        cudaFuncSetAttribute(k_quad_mma, cudaFuncAttributeMaxDynamicSharedMemorySize, QSMEM_TOTAL);
        smem_set = 1;
    }

    k_init<<<(B_ * G_ + 255) / 256, 256>>>();
    k_datacov<<<B_, 256>>>(data);
    for (int it = 0; it < 3; it++) {
        k_cov<<<dim3(B_, KSPLIT), 256>>>(A);
        k_inv<<<B_, 128>>>();
        k_mm64<<<B_, 256>>>(0);
        k_mm64<<<B_, 256>>>(1);
        k_quad_mma<<<dim3(G_ / 64, B_), 256, QSMEM_TOTAL>>>(A);
        k_mlp<<<G_, 128>>>(W1, b1, W2, b2, W3, b3, it, it == 2 ? 1 : 0, out);
    }
}

// round 4
// speedup vs baseline: 1.2065x; 1.1560x over previous
#include <cuda_runtime.h>
#include <cuda_bf16.h>
#include <cstdint>
#include <math.h>

#define B_      128
#define G_      2048
#define M_      64
#define T_      128
#define HID_    32
#define KSPLIT  4

// ================= scratch (device globals) =================
__device__ float g_C[B_ * M_ * M_];
__device__ float g_covp[KSPLIT * B_ * M_ * M_];
__device__ float g_S[B_ * M_ * M_];
__device__ float g_Tmp[B_ * M_ * M_];
__device__ float g_T1[B_ * G_];
__device__ float g_T2[B_ * G_];
__device__ float g_g[B_ * G_];
// stacked W per batch: rows 0..63 = M = S C S, rows 64..127 = S; bf16 2-term split
__device__ __nv_bfloat16 g_Whi[B_ * 128 * 64];
__device__ __nv_bfloat16 g_Wlo[B_ * 128 * 64];

// ---------------- init gamma = 1 ----------------
__global__ void k_init() {
    int i = blockIdx.x * blockDim.x + threadIdx.x;
    if (i < B_ * G_) g_g[i] = 1.0f;
}

// ---------------- C_b = data_b data_b^T / T (once) ----------------
__global__ void k_datacov(const float* __restrict__ data) {
    __shared__ float sh[M_][T_ + 1];
    int b = blockIdx.x;
    const float* d = data + (size_t)b * M_ * T_;
    for (int i = threadIdx.x; i < M_ * T_; i += blockDim.x)
        sh[i >> 7][i & 127] = d[i];
    __syncthreads();
    for (int idx = threadIdx.x; idx < M_ * M_; idx += blockDim.x) {
        int m = idx >> 6, n = idx & 63;
        float acc = 0.f;
        #pragma unroll 8
        for (int t = 0; t < T_; t++) acc += sh[m][t] * sh[n][t];
        g_C[(size_t)b * 4096 + idx] = acc * (1.0f / (float)T_);
    }
}

// ---------------- cov partial (triangular): covp[ks][b] = sum_{k in slice} g[b,k] a_k a_k^T ----------------
__global__ void __launch_bounds__(256) k_cov(const float* __restrict__ A) {
    __shared__ float shA[M_][33];
    __shared__ float shg[32];
    int b = blockIdx.x;
    int ks = blockIdx.y;
    int tid = threadIdx.x;

    // map tid -> lower-triangle tile (ty >= tx), 136 active threads
    bool act = tid < 136;
    int ty = 0, tx = 0;
    if (act) {
        float ft = (sqrtf(8.0f * (float)tid + 1.0f) - 1.0f) * 0.5f;
        ty = (int)ft;
        if ((ty + 1) * (ty + 2) / 2 <= tid) ty++;
        if (ty * (ty + 1) / 2 > tid) ty--;
        tx = tid - ty * (ty + 1) / 2;
    }

    float acc[4][4] = {};
    int kbeg = ks * (G_ / KSPLIT), kend = kbeg + (G_ / KSPLIT);
    for (int k0 = kbeg; k0 < kend; k0 += 32) {
        for (int i = tid; i < M_ * 32; i += 256) {
            int r = i >> 5, c = i & 31;
            shA[r][c] = A[(size_t)r * G_ + k0 + c];
        }
        if (tid < 32) shg[tid] = g_g[(size_t)b * G_ + k0 + tid];
        __syncthreads();
        if (act) {
            #pragma unroll 4
            for (int k = 0; k < 32; k++) {
                float gv = shg[k];
                float am[4], an[4];
                #pragma unroll
                for (int i = 0; i < 4; i++) am[i] = shA[ty * 4 + i][k] * gv;
                #pragma unroll
                for (int j = 0; j < 4; j++) an[j] = shA[tx * 4 + j][k];
                #pragma unroll
                for (int i = 0; i < 4; i++)
                    #pragma unroll
                    for (int j = 0; j < 4; j++) acc[i][j] += am[i] * an[j];
            }
        }
        __syncthreads();
    }
    if (act) {
        float* dst = g_covp + ((size_t)ks * B_ + b) * 4096;
        #pragma unroll
        for (int i = 0; i < 4; i++)
            #pragma unroll
            for (int j = 0; j < 4; j++) {
                dst[(ty * 4 + i) * 64 + tx * 4 + j] = acc[i][j];
                dst[(tx * 4 + j) * 64 + ty * 4 + i] = acc[i][j];
            }
    }
}

// ---------------- Gauss-Jordan inverse, transposed layout, vectorized, lazy right half ----------------
#define ILD 68
__global__ void __launch_bounds__(128) k_inv() {
    __shared__ float augT[128][ILD];      // [column][row]
    __shared__ __align__(16) float fbuf[M_];
    __shared__ int s_p;
    __shared__ float s_ipv;
    __shared__ int pivk[M_];
    __shared__ int used[M_];
    int b = blockIdx.x, tid = threadIdx.x;
    int j = tid;                          // owned column

    // load: augT[j][i] = cov[i][j] (+0.1 on diag); right half = identity
    for (int idx = tid; idx < M_ * M_; idx += 128) {
        int i = idx >> 6, c = idx & 63;
        float v = g_covp[(size_t)b * 4096 + idx]
                + g_covp[(size_t)(B_ + b) * 4096 + idx]
                + g_covp[(size_t)(2 * B_ + b) * 4096 + idx]
                + g_covp[(size_t)(3 * B_ + b) * 4096 + idx];
        if (i == c) v += 0.1f;
        augT[c][i] = v;
        augT[64 + c][i] = (i == c) ? 1.0f : 0.0f;
    }
    if (tid < M_) used[tid] = 0;
    __syncthreads();

    for (int k = 0; k < M_; k++) {
        if (tid < 32) {
            float v0 = used[tid]      ? -1.0f : fabsf(augT[k][tid]);
            float v1 = used[tid + 32] ? -1.0f : fabsf(augT[k][tid + 32]);
            int bi = (v1 > v0) ? (tid + 32) : tid;
            float best = fmaxf(v0, v1);
            #pragma unroll
            for (int o = 16; o > 0; o >>= 1) {
                float ob = __shfl_down_sync(0xffffffffu, best, o);
                int   oi = __shfl_down_sync(0xffffffffu, bi, o);
                if (ob > best) { best = ob; bi = oi; }
            }
            if (tid == 0) {
                s_p = bi; used[bi] = 1; pivk[k] = bi;
                s_ipv = 1.0f / augT[k][bi];
            }
        } else if (tid < 96) {
            fbuf[tid - 32] = augT[k][tid - 32];  // snapshot column k
        }
        __syncthreads();
        int p = s_p;
        float ipv = s_ipv;
        bool fresh = (j >= 64) && (p == j - 64);
        if (fresh) {
            // column was e_p; becomes -fcol*ipv with [p] = ipv
            #pragma unroll
            for (int i4 = 0; i4 < M_; i4 += 4) {
                float4 f = *(const float4*)&fbuf[i4];
                float4 v;
                v.x = -f.x * ipv; v.y = -f.y * ipv;
                v.z = -f.z * ipv; v.w = -f.w * ipv;
                *(float4*)&augT[j][i4] = v;
            }
            augT[j][p] = ipv;
        } else if (j < 64 || used[j - 64]) {
            float rn = augT[j][p] * ipv;
            #pragma unroll
            for (int i4 = 0; i4 < M_; i4 += 4) {
                float4 f = *(const float4*)&fbuf[i4];
                float4 v = *(const float4*)&augT[j][i4];
                v.x -= f.x * rn; v.y -= f.y * rn;
                v.z -= f.z * rn; v.w -= f.w * rn;
                *(float4*)&augT[j][i4] = v;
            }
            augT[j][p] = rn;
        }
        __syncthreads();
    }

    // extract: Sinv[k][c] = augT[64+c][pivk[k]]; emit bf16 split rows 64..127 of W
    for (int idx = tid; idx < M_ * M_; idx += 128) {
        int kk = idx >> 6, c = idx & 63;
        float v = augT[64 + c][pivk[kk]];
        g_S[(size_t)b * 4096 + idx] = v;
        __nv_bfloat16 h = __float2bfloat16(v);
        g_Whi[(size_t)b * 8192 + (size_t)(64 + kk) * 64 + c] = h;
        g_Wlo[(size_t)b * 8192 + (size_t)(64 + kk) * 64 + c] =
            __float2bfloat16(v - __bfloat162float(h));
    }
}

// ---------------- 64x64x64 batched GEMM: mode 0: Tmp = S@C ; mode 1: W rows 0..63 = Tmp@S ----------------
__global__ void k_mm64(int mode) {
    __shared__ float sx[M_][65];
    __shared__ float sy[M_][65];
    int b = blockIdx.x, tid = threadIdx.x;
    const float* X = (mode == 0 ? g_S : g_Tmp) + (size_t)b * 4096;
    const float* Y = (mode == 0 ? g_C : g_S) + (size_t)b * 4096;
    for (int i = tid; i < 4096; i += 256) {
        sx[i >> 6][i & 63] = X[i];
        sy[i >> 6][i & 63] = Y[i];
    }
    __syncthreads();
    int tx = tid & 15, ty = tid >> 4;
    float acc[4][4] = {};
    #pragma unroll 4
    for (int k = 0; k < M_; k++) {
        float xm[4], yn[4];
        #pragma unroll
        for (int i = 0; i < 4; i++) xm[i] = sx[ty * 4 + i][k];
        #pragma unroll
        for (int j = 0; j < 4; j++) yn[j] = sy[k][tx * 4 + j];
        #pragma unroll
        for (int i = 0; i < 4; i++)
            #pragma unroll
            for (int j = 0; j < 4; j++) acc[i][j] += xm[i] * yn[j];
    }
    if (mode == 0) {
        float* O = g_Tmp + (size_t)b * 4096;
        #pragma unroll
        for (int i = 0; i < 4; i++)
            #pragma unroll
            for (int j = 0; j < 4; j++)
                O[(ty * 4 + i) * 64 + tx * 4 + j] = acc[i][j];
    } else {
        #pragma unroll
        for (int i = 0; i < 4; i++)
            #pragma unroll
            for (int j = 0; j < 4; j++) {
                int r = ty * 4 + i, c = tx * 4 + j;
                float v = acc[i][j];
                __nv_bfloat16 h = __float2bfloat16(v);
                g_Whi[(size_t)b * 8192 + (size_t)r * 64 + c] = h;
                g_Wlo[(size_t)b * 8192 + (size_t)r * 64 + c] =
                    __float2bfloat16(v - __bfloat162float(h));
            }
    }
}

// ---------------- quadratic forms via mma.sync bf16 split ----------------
#define QLD 72
#define QOFF_WHI   0
#define QOFF_WLO   (QOFF_WHI + 128 * QLD * 2)
#define QOFF_BHI   (QOFF_WLO + 128 * QLD * 2)
#define QOFF_BLO   (QOFF_BHI + 64 * QLD * 2)
#define QOFF_SPART (QOFF_BLO + 64 * QLD * 2)
#define QSMEM_TOTAL (QOFF_SPART + 8 * 64 * 4)

__device__ __forceinline__ void mma16816(float d[4], const uint32_t a[4], const uint32_t b[2]) {
    asm volatile(
        "mma.sync.aligned.m16n8k16.row.col.f32.bf16.bf16.f32 "
        "{%0,%1,%2,%3}, {%4,%5,%6,%7}, {%8,%9}, {%0,%1,%2,%3};"
        : "+f"(d[0]), "+f"(d[1]), "+f"(d[2]), "+f"(d[3])
        : "r"(a[0]), "r"(a[1]), "r"(a[2]), "r"(a[3]), "r"(b[0]), "r"(b[1]));
}

__global__ void __launch_bounds__(256) k_quad_mma(const float* __restrict__ A) {
    extern __shared__ char smem[];
    __nv_bfloat16* sWhi = (__nv_bfloat16*)(smem + QOFF_WHI);
    __nv_bfloat16* sWlo = (__nv_bfloat16*)(smem + QOFF_WLO);
    __nv_bfloat16* sBhi = (__nv_bfloat16*)(smem + QOFF_BHI);
    __nv_bfloat16* sBlo = (__nv_bfloat16*)(smem + QOFF_BLO);
    float* spart = (float*)(smem + QOFF_SPART);

    int tid = threadIdx.x;
    int wid = tid >> 5, lane = tid & 31;
    int g0 = blockIdx.x * 64;
    int b  = blockIdx.y;

    {
        const uint4* srcH = (const uint4*)(g_Whi + (size_t)b * 8192);
        const uint4* srcL = (const uint4*)(g_Wlo + (size_t)b * 8192);
        for (int i = tid; i < 1024; i += 256) {
            int r = i >> 3, c = i & 7;
            *(uint4*)&sWhi[r * QLD + c * 8] = srcH[i];
            *(uint4*)&sWlo[r * QLD + c * 8] = srcL[i];
        }
    }
    for (int i = tid; i < 4096; i += 256) {
        int k = i >> 6, g = i & 63;
        float x = A[(size_t)k * G_ + g0 + g];
        __nv_bfloat16 h = __float2bfloat16(x);
        sBhi[g * QLD + k] = h;
        sBlo[g * QLD + k] = __float2bfloat16(x - __bfloat162float(h));
    }
    __syncthreads();

    int wrow = wid * 16;
    int r0 = wrow + (lane >> 2);
    int cq = (lane & 3) * 2;

    float d[8][4];
    #pragma unroll
    for (int t = 0; t < 8; t++)
        #pragma unroll
        for (int j = 0; j < 4; j++) d[t][j] = 0.0f;

    #pragma unroll
    for (int sp = 0; sp < 3; sp++) {
        const __nv_bfloat16* Wsrc = (sp == 2) ? sWlo : sWhi;
        const __nv_bfloat16* Bsrc = (sp == 1) ? sBlo : sBhi;
        #pragma unroll
        for (int ks = 0; ks < 4; ks++) {
            int kb = ks * 16;
            uint32_t a[4];
            a[0] = *(const uint32_t*)&Wsrc[r0 * QLD + kb + cq];
            a[1] = *(const uint32_t*)&Wsrc[(r0 + 8) * QLD + kb + cq];
            a[2] = *(const uint32_t*)&Wsrc[r0 * QLD + kb + cq + 8];
            a[3] = *(const uint32_t*)&Wsrc[(r0 + 8) * QLD + kb + cq + 8];
            int n = lane >> 2;
            #pragma unroll
            for (int t = 0; t < 8; t++) {
                uint32_t bb[2];
                bb[0] = *(const uint32_t*)&Bsrc[(t * 8 + n) * QLD + kb + cq];
                bb[1] = *(const uint32_t*)&Bsrc[(t * 8 + n) * QLD + kb + cq + 8];
                mma16816(d[t], a, bb);
            }
        }
    }

    int mbase = wrow & 63;
    int m0 = mbase + (lane >> 2);
    #pragma unroll
    for (int t = 0; t < 8; t++) {
        int g = t * 8 + cq;
        float a00 = __bfloat162float(sBhi[g * QLD + m0])       + __bfloat162float(sBlo[g * QLD + m0]);
        float a10 = __bfloat162float(sBhi[g * QLD + m0 + 8])   + __bfloat162float(sBlo[g * QLD + m0 + 8]);
        float a01 = __bfloat162float(sBhi[(g + 1) * QLD + m0]) + __bfloat162float(sBlo[(g + 1) * QLD + m0]);
        float a11 = __bfloat162float(sBhi[(g + 1) * QLD + m0 + 8]) + __bfloat162float(sBlo[(g + 1) * QLD + m0 + 8]);
        float p0 = d[t][0] * a00 + d[t][2] * a10;
        float p1 = d[t][1] * a01 + d[t][3] * a11;
        #pragma unroll
        for (int o = 4; o < 32; o <<= 1) {
            p0 += __shfl_xor_sync(0xffffffffu, p0, o);
            p1 += __shfl_xor_sync(0xffffffffu, p1, o);
        }
        if (lane < 4) {
            spart[wid * 64 + g] = p0;
            spart[wid * 64 + g + 1] = p1;
        }
    }
    __syncthreads();
    if (tid < 64) {
        int g = tid;
        float t1 = spart[g] + spart[64 + g] + spart[128 + g] + spart[192 + g];
        float t2 = spart[256 + g] + spart[320 + g] + spart[384 + g] + spart[448 + g];
        g_T1[(size_t)b * G_ + g0 + g] = t1;
        g_T2[(size_t)b * G_ + g0 + g] = fabsf(t2);
    }
}

// ---------------- per-gridpoint MLP ----------------
__global__ void k_mlp(const float* __restrict__ W1, const float* __restrict__ B1,
                      const float* __restrict__ W2, const float* __restrict__ B2,
                      const float* __restrict__ W3, const float* __restrict__ B3,
                      int it, int last, float* __restrict__ out) {
    int g = blockIdx.x;
    int b = threadIdx.x;
    __shared__ float sW1[96], sB1[32], sW2[1024], sB2[32], sW3[32], sB3;
    size_t gidx = (size_t)it * G_ + g;
    const float* w1 = W1 + gidx * 96;
    const float* w2 = W2 + gidx * 1024;
    if (b < 96) sW1[b] = w1[b];
    if (b < 32) {
        sB1[b] = B1[gidx * 32 + b];
        sB2[b] = B2[gidx * 32 + b];
        sW3[b] = W3[gidx * 32 + b];
    }
    if (b == 0) sB3 = B3[gidx];
    for (int i = b; i < 1024; i += 128) sW2[i] = w2[i];
    __syncthreads();

    float x0 = g_T1[(size_t)b * G_ + g];
    float x1 = g_T2[(size_t)b * G_ + g];
    float x2 = g_g[(size_t)b * G_ + g];

    float h[HID_];
    #pragma unroll
    for (int j = 0; j < HID_; j++) {
        float v = x0 * sW1[j] + x1 * sW1[32 + j] + x2 * sW1[64 + j] + sB1[j];
        h[j] = fmaxf(v, 0.0f);
    }
    float h2[HID_];
    #pragma unroll
    for (int j = 0; j < HID_; j++) h2[j] = sB2[j];
    #pragma unroll
    for (int j = 0; j < HID_; j++) {
        float hv = h[j];
        #pragma unroll
        for (int k = 0; k < HID_; k++) h2[k] += hv * sW2[j * 32 + k];
    }
    float o = sB3;
    #pragma unroll
    for (int k = 0; k < HID_; k++) o += fmaxf(h2[k], 0.0f) * sW3[k];

    if (last) out[(size_t)b * G_ + g] = o;
    else      g_g[(size_t)b * G_ + g] = o;
}

// ---------------- launch ----------------
extern "C" void kernel_launch(void* const* d_in, const int* in_sizes, int n_in,
                              void* d_out, int out_size) {
    const float* data = (const float*)d_in[0];
    const float* A    = (const float*)d_in[1];
    const float* W1   = (const float*)d_in[2];
    const float* b1   = (const float*)d_in[3];
    const float* W2   = (const float*)d_in[4];
    const float* b2   = (const float*)d_in[5];
    const float* W3   = (const float*)d_in[6];
    const float* b3   = (const float*)d_in[7];
    float* out = (float*)d_out;

    static int smem_set = 0;
    if (!smem_set) {
        cudaFuncSetAttribute(k_quad_mma, cudaFuncAttributeMaxDynamicSharedMemorySize, QSMEM_TOTAL);
        smem_set = 1;
    }

    k_init<<<(B_ * G_ + 255) / 256, 256>>>();
    k_datacov<<<B_, 256>>>(data);
    for (int it = 0; it < 3; it++) {
        k_cov<<<dim3(B_, KSPLIT), 256>>>(A);
        k_inv<<<B_, 128>>>();
        k_mm64<<<B_, 256>>>(0);
        k_mm64<<<B_, 256>>>(1);
        k_quad_mma<<<dim3(G_ / 64, B_), 256, QSMEM_TOTAL>>>(A);
        k_mlp<<<G_, 128>>>(W1, b1, W2, b2, W3, b3, it, it == 2 ? 1 : 0, out);
    }
}

// round 5
// speedup vs baseline: 1.4267x; 1.1825x over previous
#include <cuda_runtime.h>
#include <cuda_bf16.h>
#include <cstdint>
#include <math.h>

#define B_      128
#define G_      2048
#define M_      64
#define T_      128
#define HID_    32
#define KSPLIT  4

// ================= scratch (device globals) =================
__device__ float g_C[B_ * M_ * M_];
__device__ float g_covp[KSPLIT * B_ * M_ * M_];
__device__ float g_S[B_ * M_ * M_];
__device__ float g_T1[B_ * G_];
__device__ float g_T2[B_ * G_];
__device__ float g_g[B_ * G_];
// stacked W per batch: rows 0..63 = M = S C S, rows 64..127 = S; bf16 2-term split
__device__ __nv_bfloat16 g_Whi[B_ * 128 * 64];
__device__ __nv_bfloat16 g_Wlo[B_ * 128 * 64];

// ---------------- init gamma = 1 ----------------
__global__ void k_init() {
    int i = blockIdx.x * blockDim.x + threadIdx.x;
    if (i < B_ * G_) g_g[i] = 1.0f;
}

// ---------------- C_b = data_b data_b^T / T (once) ----------------
__global__ void k_datacov(const float* __restrict__ data) {
    __shared__ float sh[M_][T_ + 1];
    int b = blockIdx.x;
    const float* d = data + (size_t)b * M_ * T_;
    for (int i = threadIdx.x; i < M_ * T_; i += blockDim.x)
        sh[i >> 7][i & 127] = d[i];
    __syncthreads();
    for (int idx = threadIdx.x; idx < M_ * M_; idx += blockDim.x) {
        int m = idx >> 6, n = idx & 63;
        float acc = 0.f;
        #pragma unroll 8
        for (int t = 0; t < T_; t++) acc += sh[m][t] * sh[n][t];
        g_C[(size_t)b * 4096 + idx] = acc * (1.0f / (float)T_);
    }
}

// ---------------- cov partial (triangular) ----------------
__global__ void __launch_bounds__(256) k_cov(const float* __restrict__ A) {
    __shared__ float shA[M_][33];
    __shared__ float shg[32];
    int b = blockIdx.x;
    int ks = blockIdx.y;
    int tid = threadIdx.x;

    bool act = tid < 136;
    int ty = 0, tx = 0;
    if (act) {
        float ft = (sqrtf(8.0f * (float)tid + 1.0f) - 1.0f) * 0.5f;
        ty = (int)ft;
        if ((ty + 1) * (ty + 2) / 2 <= tid) ty++;
        if (ty * (ty + 1) / 2 > tid) ty--;
        tx = tid - ty * (ty + 1) / 2;
    }

    float acc[4][4] = {};
    int kbeg = ks * (G_ / KSPLIT), kend = kbeg + (G_ / KSPLIT);
    for (int k0 = kbeg; k0 < kend; k0 += 32) {
        for (int i = tid; i < M_ * 32; i += 256) {
            int r = i >> 5, c = i & 31;
            shA[r][c] = A[(size_t)r * G_ + k0 + c];
        }
        if (tid < 32) shg[tid] = g_g[(size_t)b * G_ + k0 + tid];
        __syncthreads();
        if (act) {
            #pragma unroll 4
            for (int k = 0; k < 32; k++) {
                float gv = shg[k];
                float am[4], an[4];
                #pragma unroll
                for (int i = 0; i < 4; i++) am[i] = shA[ty * 4 + i][k] * gv;
                #pragma unroll
                for (int j = 0; j < 4; j++) an[j] = shA[tx * 4 + j][k];
                #pragma unroll
                for (int i = 0; i < 4; i++)
                    #pragma unroll
                    for (int j = 0; j < 4; j++) acc[i][j] += am[i] * an[j];
            }
        }
        __syncthreads();
    }
    if (act) {
        float* dst = g_covp + ((size_t)ks * B_ + b) * 4096;
        #pragma unroll
        for (int i = 0; i < 4; i++)
            #pragma unroll
            for (int j = 0; j < 4; j++) {
                dst[(ty * 4 + i) * 64 + tx * 4 + j] = acc[i][j];
                dst[(tx * 4 + j) * 64 + ty * 4 + i] = acc[i][j];
            }
    }
}

// ---------------- Gauss-Jordan inverse, panel-2 (rank-2 updates), transposed ----------------
#define ILD 68
__global__ void __launch_bounds__(128) k_inv() {
    __shared__ float augT[128][ILD];                 // [column][row]
    __shared__ __align__(16) float f1[M_];
    __shared__ __align__(16) float f2e[M_];
    __shared__ __align__(16) float f2r[M_];
    __shared__ int s_p1, s_p2;
    __shared__ float s_ip1, s_ip2;
    __shared__ int pivk[M_];
    __shared__ int used[M_];
    int b = blockIdx.x, tid = threadIdx.x;
    int wid = tid >> 5, lane = tid & 31;
    int j = tid;                                     // owned column

    for (int idx = tid; idx < M_ * M_; idx += 128) {
        int i = idx >> 6, c = idx & 63;
        float v = g_covp[(size_t)b * 4096 + idx]
                + g_covp[(size_t)(B_ + b) * 4096 + idx]
                + g_covp[(size_t)(2 * B_ + b) * 4096 + idx]
                + g_covp[(size_t)(3 * B_ + b) * 4096 + idx];
        if (i == c) v += 0.1f;
        augT[c][i] = v;
        augT[64 + c][i] = (i == c) ? 1.0f : 0.0f;
    }
    if (tid < M_) used[tid] = 0;
    __syncthreads();

    for (int k = 0; k < M_; k += 2) {
        // -------- Phase A: pivot for col k (warp0) || snapshots (warps 1,2)
        if (wid == 0) {
            float sv0 = augT[k][lane], sv1 = augT[k][lane + 32];
            float v0 = used[lane]      ? -1.0f : fabsf(sv0);
            float v1 = used[lane + 32] ? -1.0f : fabsf(sv1);
            int bi; float best, bv;
            if (v1 > v0) { best = v1; bi = lane + 32; bv = sv1; }
            else         { best = v0; bi = lane;      bv = sv0; }
            #pragma unroll
            for (int o = 16; o > 0; o >>= 1) {
                float ob = __shfl_down_sync(0xffffffffu, best, o);
                int   oi = __shfl_down_sync(0xffffffffu, bi, o);
                float ov = __shfl_down_sync(0xffffffffu, bv, o);
                if (ob > best) { best = ob; bi = oi; bv = ov; }
            }
            if (lane == 0) {
                s_p1 = bi; used[bi] = 1; pivk[k] = bi;
                s_ip1 = 1.0f / bv;
            }
        } else if (wid == 1) {
            f1[lane] = augT[k][lane];
            f1[lane + 32] = augT[k][lane + 32];
        } else if (wid == 2) {
            f2r[lane] = augT[k + 1][lane];
            f2r[lane + 32] = augT[k + 1][lane + 32];
        }
        __syncthreads();

        // -------- Phase B: warp0 eliminates col k+1 wrt pivot1, finds pivot2
        if (wid == 0) {
            int p1 = s_p1; float ip1 = s_ip1;
            float rn12 = f2r[p1] * ip1;
            float e0 = f2r[lane]      - f1[lane]      * rn12;
            float e1 = f2r[lane + 32] - f1[lane + 32] * rn12;
            if (lane == p1)      e0 = rn12;
            if (lane + 32 == p1) e1 = rn12;
            f2e[lane] = e0;
            f2e[lane + 32] = e1;
            float v0 = used[lane]      ? -1.0f : fabsf(e0);
            float v1 = used[lane + 32] ? -1.0f : fabsf(e1);
            int bi; float best, bv;
            if (v1 > v0) { best = v1; bi = lane + 32; bv = e1; }
            else         { best = v0; bi = lane;      bv = e0; }
            #pragma unroll
            for (int o = 16; o > 0; o >>= 1) {
                float ob = __shfl_down_sync(0xffffffffu, best, o);
                int   oi = __shfl_down_sync(0xffffffffu, bi, o);
                float ov = __shfl_down_sync(0xffffffffu, bv, o);
                if (ob > best) { best = ob; bi = oi; bv = ov; }
            }
            if (lane == 0) {
                s_p2 = bi; used[bi] = 1; pivk[k + 1] = bi;
                s_ip2 = 1.0f / bv;
            }
        }
        __syncthreads();

        // -------- Phase C: rank-2 update, all columns
        {
            int p1 = s_p1, p2 = s_p2;
            float ip1 = s_ip1, ip2 = s_ip2;
            float rn1 = augT[j][p1] * ip1;
            float rn2 = (augT[j][p2] - f1[p2] * rn1) * ip2;
            if (rn1 != 0.0f || rn2 != 0.0f) {
                #pragma unroll
                for (int i4 = 0; i4 < M_; i4 += 4) {
                    float4 a  = *(const float4*)&f1[i4];
                    float4 c2 = *(const float4*)&f2e[i4];
                    float4 v  = *(const float4*)&augT[j][i4];
                    v.x -= a.x * rn1 + c2.x * rn2;
                    v.y -= a.y * rn1 + c2.y * rn2;
                    v.z -= a.z * rn1 + c2.z * rn2;
                    v.w -= a.w * rn1 + c2.w * rn2;
                    *(float4*)&augT[j][i4] = v;
                }
                augT[j][p1] = rn1 - f2e[p1] * rn2;
                augT[j][p2] = rn2;
            }
        }
        __syncthreads();
    }

    // extract: Sinv[k][c] = augT[64+c][pivk[k]]; emit bf16 split rows 64..127 of W
    for (int idx = tid; idx < M_ * M_; idx += 128) {
        int kk = idx >> 6, c = idx & 63;
        float v = augT[64 + c][pivk[kk]];
        g_S[(size_t)b * 4096 + idx] = v;
        __nv_bfloat16 h = __float2bfloat16(v);
        g_Whi[(size_t)b * 8192 + (size_t)(64 + kk) * 64 + c] = h;
        g_Wlo[(size_t)b * 8192 + (size_t)(64 + kk) * 64 + c] =
            __float2bfloat16(v - __bfloat162float(h));
    }
}

// ---------------- fused 64x64x64 x2: Tmp = S@C (smem), M = Tmp@S -> W rows 0..63 ----------------
#define MMLDS (M_ * 65)
#define MMSMEM ((MMLDS * 2 + M_ * M_) * 4)
__global__ void __launch_bounds__(256) k_mm64_fused() {
    extern __shared__ float sm[];
    float* sS = sm;                       // [64][65] (col-accessed, padded)
    float* sT = sm + MMLDS;               // [64][65]
    float* sC = sm + MMLDS * 2;           // [64][64] (row-accessed)
    int b = blockIdx.x, tid = threadIdx.x;
    const float* S = g_S + (size_t)b * 4096;
    const float* C = g_C + (size_t)b * 4096;
    for (int i = tid; i < 4096; i += 256) {
        int r = i >> 6, c = i & 63;
        sS[r * 65 + c] = S[i];
        sC[i] = C[i];
    }
    __syncthreads();
    int tx = tid & 15, ty = tid >> 4;
    // GEMM1: T = S @ C
    {
        float acc[4][4] = {};
        #pragma unroll 4
        for (int k = 0; k < M_; k++) {
            float xm[4], yn[4];
            #pragma unroll
            for (int i = 0; i < 4; i++) xm[i] = sS[(ty * 4 + i) * 65 + k];
            #pragma unroll
            for (int jj = 0; jj < 4; jj++) yn[jj] = sC[k * 64 + tx * 4 + jj];
            #pragma unroll
            for (int i = 0; i < 4; i++)
                #pragma unroll
                for (int jj = 0; jj < 4; jj++) acc[i][jj] += xm[i] * yn[jj];
        }
        #pragma unroll
        for (int i = 0; i < 4; i++)
            #pragma unroll
            for (int jj = 0; jj < 4; jj++)
                sT[(ty * 4 + i) * 65 + tx * 4 + jj] = acc[i][jj];
    }
    __syncthreads();
    // GEMM2: M = T @ S -> bf16 split W rows 0..63
    {
        float acc[4][4] = {};
        #pragma unroll 4
        for (int k = 0; k < M_; k++) {
            float xm[4], yn[4];
            #pragma unroll
            for (int i = 0; i < 4; i++) xm[i] = sT[(ty * 4 + i) * 65 + k];
            #pragma unroll
            for (int jj = 0; jj < 4; jj++) yn[jj] = sS[k * 65 + tx * 4 + jj];
            #pragma unroll
            for (int i = 0; i < 4; i++)
                #pragma unroll
                for (int jj = 0; jj < 4; jj++) acc[i][jj] += xm[i] * yn[jj];
        }
        #pragma unroll
        for (int i = 0; i < 4; i++)
            #pragma unroll
            for (int jj = 0; jj < 4; jj++) {
                int r = ty * 4 + i, c = tx * 4 + jj;
                float v = acc[i][jj];
                __nv_bfloat16 h = __float2bfloat16(v);
                g_Whi[(size_t)b * 8192 + (size_t)r * 64 + c] = h;
                g_Wlo[(size_t)b * 8192 + (size_t)r * 64 + c] =
                    __float2bfloat16(v - __bfloat162float(h));
            }
    }
}

// ---------------- quadratic forms via mma.sync bf16 split ----------------
#define QLD 72
#define QOFF_WHI   0
#define QOFF_WLO   (QOFF_WHI + 128 * QLD * 2)
#define QOFF_BHI   (QOFF_WLO + 128 * QLD * 2)
#define QOFF_BLO   (QOFF_BHI + 64 * QLD * 2)
#define QOFF_SPART (QOFF_BLO + 64 * QLD * 2)
#define QSMEM_TOTAL (QOFF_SPART + 8 * 64 * 4)

__device__ __forceinline__ void mma16816(float d[4], const uint32_t a[4], const uint32_t b[2]) {
    asm volatile(
        "mma.sync.aligned.m16n8k16.row.col.f32.bf16.bf16.f32 "
        "{%0,%1,%2,%3}, {%4,%5,%6,%7}, {%8,%9}, {%0,%1,%2,%3};"
        : "+f"(d[0]), "+f"(d[1]), "+f"(d[2]), "+f"(d[3])
        : "r"(a[0]), "r"(a[1]), "r"(a[2]), "r"(a[3]), "r"(b[0]), "r"(b[1]));
}

__global__ void __launch_bounds__(256) k_quad_mma(const float* __restrict__ A) {
    extern __shared__ char smem[];
    __nv_bfloat16* sWhi = (__nv_bfloat16*)(smem + QOFF_WHI);
    __nv_bfloat16* sWlo = (__nv_bfloat16*)(smem + QOFF_WLO);
    __nv_bfloat16* sBhi = (__nv_bfloat16*)(smem + QOFF_BHI);
    __nv_bfloat16* sBlo = (__nv_bfloat16*)(smem + QOFF_BLO);
    float* spart = (float*)(smem + QOFF_SPART);

    int tid = threadIdx.x;
    int wid = tid >> 5, lane = tid & 31;
    int g0 = blockIdx.x * 64;
    int b  = blockIdx.y;

    {
        const uint4* srcH = (const uint4*)(g_Whi + (size_t)b * 8192);
        const uint4* srcL = (const uint4*)(g_Wlo + (size_t)b * 8192);
        for (int i = tid; i < 1024; i += 256) {
            int r = i >> 3, c = i & 7;
            *(uint4*)&sWhi[r * QLD + c * 8] = srcH[i];
            *(uint4*)&sWlo[r * QLD + c * 8] = srcL[i];
        }
    }
    for (int i = tid; i < 4096; i += 256) {
        int k = i >> 6, g = i & 63;
        float x = A[(size_t)k * G_ + g0 + g];
        __nv_bfloat16 h = __float2bfloat16(x);
        sBhi[g * QLD + k] = h;
        sBlo[g * QLD + k] = __float2bfloat16(x - __bfloat162float(h));
    }
    __syncthreads();

    int wrow = wid * 16;
    int r0 = wrow + (lane >> 2);
    int cq = (lane & 3) * 2;

    float d[8][4];
    #pragma unroll
    for (int t = 0; t < 8; t++)
        #pragma unroll
        for (int j = 0; j < 4; j++) d[t][j] = 0.0f;

    #pragma unroll
    for (int sp = 0; sp < 3; sp++) {
        const __nv_bfloat16* Wsrc = (sp == 2) ? sWlo : sWhi;
        const __nv_bfloat16* Bsrc = (sp == 1) ? sBlo : sBhi;
        #pragma unroll
        for (int ks = 0; ks < 4; ks++) {
            int kb = ks * 16;
            uint32_t a[4];
            a[0] = *(const uint32_t*)&Wsrc[r0 * QLD + kb + cq];
            a[1] = *(const uint32_t*)&Wsrc[(r0 + 8) * QLD + kb + cq];
            a[2] = *(const uint32_t*)&Wsrc[r0 * QLD + kb + cq + 8];
            a[3] = *(const uint32_t*)&Wsrc[(r0 + 8) * QLD + kb + cq + 8];
            int n = lane >> 2;
            #pragma unroll
            for (int t = 0; t < 8; t++) {
                uint32_t bb[2];
                bb[0] = *(const uint32_t*)&Bsrc[(t * 8 + n) * QLD + kb + cq];
                bb[1] = *(const uint32_t*)&Bsrc[(t * 8 + n) * QLD + kb + cq + 8];
                mma16816(d[t], a, bb);
            }
        }
    }

    int mbase = wrow & 63;
    int m0 = mbase + (lane >> 2);
    #pragma unroll
    for (int t = 0; t < 8; t++) {
        int g = t * 8 + cq;
        float a00 = __bfloat162float(sBhi[g * QLD + m0])       + __bfloat162float(sBlo[g * QLD + m0]);
        float a10 = __bfloat162float(sBhi[g * QLD + m0 + 8])   + __bfloat162float(sBlo[g * QLD + m0 + 8]);
        float a01 = __bfloat162float(sBhi[(g + 1) * QLD + m0]) + __bfloat162float(sBlo[(g + 1) * QLD + m0]);
        float a11 = __bfloat162float(sBhi[(g + 1) * QLD + m0 + 8]) + __bfloat162float(sBlo[(g + 1) * QLD + m0 + 8]);
        float p0 = d[t][0] * a00 + d[t][2] * a10;
        float p1 = d[t][1] * a01 + d[t][3] * a11;
        #pragma unroll
        for (int o = 4; o < 32; o <<= 1) {
            p0 += __shfl_xor_sync(0xffffffffu, p0, o);
            p1 += __shfl_xor_sync(0xffffffffu, p1, o);
        }
        if (lane < 4) {
            spart[wid * 64 + g] = p0;
            spart[wid * 64 + g + 1] = p1;
        }
    }
    __syncthreads();
    if (tid < 64) {
        int g = tid;
        float t1 = spart[g] + spart[64 + g] + spart[128 + g] + spart[192 + g];
        float t2 = spart[256 + g] + spart[320 + g] + spart[384 + g] + spart[448 + g];
        g_T1[(size_t)b * G_ + g0 + g] = t1;
        g_T2[(size_t)b * G_ + g0 + g] = fabsf(t2);
    }
}

// ---------------- per-gridpoint MLP ----------------
__global__ void k_mlp(const float* __restrict__ W1, const float* __restrict__ B1,
                      const float* __restrict__ W2, const float* __restrict__ B2,
                      const float* __restrict__ W3, const float* __restrict__ B3,
                      int it, int last, float* __restrict__ out) {
    int g = blockIdx.x;
    int b = threadIdx.x;
    __shared__ float sW1[96], sB1[32], sW2[1024], sB2[32], sW3[32], sB3;
    size_t gidx = (size_t)it * G_ + g;
    const float* w1 = W1 + gidx * 96;
    const float* w2 = W2 + gidx * 1024;
    if (b < 96) sW1[b] = w1[b];
    if (b < 32) {
        sB1[b] = B1[gidx * 32 + b];
        sB2[b] = B2[gidx * 32 + b];
        sW3[b] = W3[gidx * 32 + b];
    }
    if (b == 0) sB3 = B3[gidx];
    for (int i = b; i < 1024; i += 128) sW2[i] = w2[i];
    __syncthreads();

    float x0 = g_T1[(size_t)b * G_ + g];
    float x1 = g_T2[(size_t)b * G_ + g];
    float x2 = g_g[(size_t)b * G_ + g];

    float h[HID_];
    #pragma unroll
    for (int j = 0; j < HID_; j++) {
        float v = x0 * sW1[j] + x1 * sW1[32 + j] + x2 * sW1[64 + j] + sB1[j];
        h[j] = fmaxf(v, 0.0f);
    }
    float h2[HID_];
    #pragma unroll
    for (int j = 0; j < HID_; j++) h2[j] = sB2[j];
    #pragma unroll
    for (int j = 0; j < HID_; j++) {
        float hv = h[j];
        #pragma unroll
        for (int k = 0; k < HID_; k++) h2[k] += hv * sW2[j * 32 + k];
    }
    float o = sB3;
    #pragma unroll
    for (int k = 0; k < HID_; k++) o += fmaxf(h2[k], 0.0f) * sW3[k];

    if (last) out[(size_t)b * G_ + g] = o;
    else      g_g[(size_t)b * G_ + g] = o;
}

// ---------------- launch ----------------
extern "C" void kernel_launch(void* const* d_in, const int* in_sizes, int n_in,
                              void* d_out, int out_size) {
    const float* data = (const float*)d_in[0];
    const float* A    = (const float*)d_in[1];
    const float* W1   = (const float*)d_in[2];
    const float* b1   = (const float*)d_in[3];
    const float* W2   = (const float*)d_in[4];
    const float* b2   = (const float*)d_in[5];
    const float* W3   = (const float*)d_in[6];
    const float* b3   = (const float*)d_in[7];
    float* out = (float*)d_out;

    static int smem_set = 0;
    if (!smem_set) {
        cudaFuncSetAttribute(k_quad_mma, cudaFuncAttributeMaxDynamicSharedMemorySize, QSMEM_TOTAL);
        cudaFuncSetAttribute(k_mm64_fused, cudaFuncAttributeMaxDynamicSharedMemorySize, MMSMEM);
        smem_set = 1;
    }

    k_init<<<(B_ * G_ + 255) / 256, 256>>>();
    k_datacov<<<B_, 256>>>(data);
    for (int it = 0; it < 3; it++) {
        k_cov<<<dim3(B_, KSPLIT), 256>>>(A);
        k_inv<<<B_, 128>>>();
        k_mm64_fused<<<B_, 256, MMSMEM>>>();
        k_quad_mma<<<dim3(G_ / 64, B_), 256, QSMEM_TOTAL>>>(A);
        k_mlp<<<G_, 128>>>(W1, b1, W2, b2, W3, b3, it, it == 2 ? 1 : 0, out);
    }
}

// round 8
// speedup vs baseline: 1.4384x; 1.0082x over previous
#include <cuda_runtime.h>
#include <cuda_bf16.h>
#include <cstdint>
#include <math.h>

#define B_      128
#define G_      2048
#define M_      64
#define T_      128
#define HID_    32
#define KSPLIT  4

// ================= scratch (device globals) =================
__device__ float g_C[B_ * M_ * M_];
__device__ float g_covp[KSPLIT * B_ * M_ * M_];
__device__ float g_S[B_ * M_ * M_];
__device__ float g_T1[B_ * G_];
__device__ float g_T2[B_ * G_];
__device__ float g_g[B_ * G_];
// stacked W per batch: rows 0..63 = M = S C S, rows 64..127 = S; bf16 2-term split
__device__ __nv_bfloat16 g_Whi[B_ * 128 * 64];
__device__ __nv_bfloat16 g_Wlo[B_ * 128 * 64];

// ---------------- init gamma = 1 ----------------
__global__ void k_init() {
    int i = blockIdx.x * blockDim.x + threadIdx.x;
    if (i < B_ * G_) g_g[i] = 1.0f;
}

// ---------------- C_b = data_b data_b^T / T (once) ----------------
__global__ void k_datacov(const float* __restrict__ data) {
    __shared__ float sh[M_][T_ + 1];
    int b = blockIdx.x;
    const float* d = data + (size_t)b * M_ * T_;
    for (int i = threadIdx.x; i < M_ * T_; i += blockDim.x)
        sh[i >> 7][i & 127] = d[i];
    __syncthreads();
    for (int idx = threadIdx.x; idx < M_ * M_; idx += blockDim.x) {
        int m = idx >> 6, n = idx & 63;
        float acc = 0.f;
        #pragma unroll 8
        for (int t = 0; t < T_; t++) acc += sh[m][t] * sh[n][t];
        g_C[(size_t)b * 4096 + idx] = acc * (1.0f / (float)T_);
    }
}

// ---------------- cov partial (triangular, fp32 SIMT — known good) ----------------
__global__ void __launch_bounds__(256) k_cov(const float* __restrict__ A) {
    __shared__ float shA[M_][33];
    __shared__ float shg[32];
    int b = blockIdx.x;
    int ks = blockIdx.y;
    int tid = threadIdx.x;

    bool act = tid < 136;
    int ty = 0, tx = 0;
    if (act) {
        float ft = (sqrtf(8.0f * (float)tid + 1.0f) - 1.0f) * 0.5f;
        ty = (int)ft;
        if ((ty + 1) * (ty + 2) / 2 <= tid) ty++;
        if (ty * (ty + 1) / 2 > tid) ty--;
        tx = tid - ty * (ty + 1) / 2;
    }

    float acc[4][4] = {};
    int kbeg = ks * (G_ / KSPLIT), kend = kbeg + (G_ / KSPLIT);
    for (int k0 = kbeg; k0 < kend; k0 += 32) {
        for (int i = tid; i < M_ * 32; i += 256) {
            int r = i >> 5, c = i & 31;
            shA[r][c] = A[(size_t)r * G_ + k0 + c];
        }
        if (tid < 32) shg[tid] = g_g[(size_t)b * G_ + k0 + tid];
        __syncthreads();
        if (act) {
            #pragma unroll 4
            for (int k = 0; k < 32; k++) {
                float gv = shg[k];
                float am[4], an[4];
                #pragma unroll
                for (int i = 0; i < 4; i++) am[i] = shA[ty * 4 + i][k] * gv;
                #pragma unroll
                for (int j = 0; j < 4; j++) an[j] = shA[tx * 4 + j][k];
                #pragma unroll
                for (int i = 0; i < 4; i++)
                    #pragma unroll
                    for (int j = 0; j < 4; j++) acc[i][j] += am[i] * an[j];
            }
        }
        __syncthreads();
    }
    if (act) {
        float* dst = g_covp + ((size_t)ks * B_ + b) * 4096;
        #pragma unroll
        for (int i = 0; i < 4; i++)
            #pragma unroll
            for (int j = 0; j < 4; j++) {
                dst[(ty * 4 + i) * 64 + tx * 4 + j] = acc[i][j];
                dst[(tx * 4 + j) * 64 + ty * 4 + i] = acc[i][j];
            }
    }
}

// ---------------- Gauss-Jordan inverse, panel-2, 2 batches per block ----------------
#define ILD 68
#define ISMEM (2 * 128 * ILD * 4)
__global__ void __launch_bounds__(128) k_inv2() {
    extern __shared__ float ish[];
    float* aug0 = ish;                 // [128 col][ILD row]
    float* aug1 = ish + 128 * ILD;
    __shared__ __align__(16) float f1a[M_], f2ra[M_], f2ea[M_];
    __shared__ __align__(16) float f1b[M_], f2rb[M_], f2eb[M_];
    __shared__ int sp1a, sp2a, sp1b, sp2b;
    __shared__ float sip1a, sip2a, sip1b, sip2b;
    __shared__ int pivka[M_], pivkb[M_];
    __shared__ int useda[M_], usedb[M_];
    int bb = blockIdx.x * 2;
    int tid = threadIdx.x;
    int wid = tid >> 5, lane = tid & 31;
    int j = tid;

    for (int idx = tid; idx < M_ * M_; idx += 128) {
        int i = idx >> 6, c = idx & 63;
        float v0 = g_covp[(size_t)bb * 4096 + idx]
                 + g_covp[(size_t)(B_ + bb) * 4096 + idx]
                 + g_covp[(size_t)(2 * B_ + bb) * 4096 + idx]
                 + g_covp[(size_t)(3 * B_ + bb) * 4096 + idx];
        float v1 = g_covp[(size_t)(bb + 1) * 4096 + idx]
                 + g_covp[(size_t)(B_ + bb + 1) * 4096 + idx]
                 + g_covp[(size_t)(2 * B_ + bb + 1) * 4096 + idx]
                 + g_covp[(size_t)(3 * B_ + bb + 1) * 4096 + idx];
        if (i == c) { v0 += 0.1f; v1 += 0.1f; }
        float idv = (i == c) ? 1.0f : 0.0f;
        aug0[c * ILD + i] = v0;  aug0[(64 + c) * ILD + i] = idv;
        aug1[c * ILD + i] = v1;  aug1[(64 + c) * ILD + i] = idv;
    }
    if (tid < M_) { useda[tid] = 0; usedb[tid] = 0; }
    __syncthreads();

    for (int k = 0; k < M_; k += 2) {
        // Phase A: pivot-1 searches (warps 0,1) || snapshots (warps 2,3)
        if (wid == 0 || wid == 1) {
            float* aug = wid ? aug1 : aug0;
            int* used = wid ? usedb : useda;
            float sv0 = aug[k * ILD + lane], sv1 = aug[k * ILD + lane + 32];
            float v0 = used[lane]      ? -1.0f : fabsf(sv0);
            float v1 = used[lane + 32] ? -1.0f : fabsf(sv1);
            int bi; float best, bv;
            if (v1 > v0) { best = v1; bi = lane + 32; bv = sv1; }
            else         { best = v0; bi = lane;      bv = sv0; }
            #pragma unroll
            for (int o = 16; o > 0; o >>= 1) {
                float ob = __shfl_down_sync(0xffffffffu, best, o);
                int   oi = __shfl_down_sync(0xffffffffu, bi, o);
                float ov = __shfl_down_sync(0xffffffffu, bv, o);
                if (ob > best) { best = ob; bi = oi; bv = ov; }
            }
            if (lane == 0) {
                used[bi] = 1;
                if (wid == 0) { sp1a = bi; pivka[k] = bi; sip1a = 1.0f / bv; }
                else          { sp1b = bi; pivkb[k] = bi; sip1b = 1.0f / bv; }
            }
        } else if (wid == 2) {
            f1a[lane] = aug0[k * ILD + lane];
            f1a[lane + 32] = aug0[k * ILD + lane + 32];
            f2ra[lane] = aug0[(k + 1) * ILD + lane];
            f2ra[lane + 32] = aug0[(k + 1) * ILD + lane + 32];
        } else {
            f1b[lane] = aug1[k * ILD + lane];
            f1b[lane + 32] = aug1[k * ILD + lane + 32];
            f2rb[lane] = aug1[(k + 1) * ILD + lane];
            f2rb[lane + 32] = aug1[(k + 1) * ILD + lane + 32];
        }
        __syncthreads();

        // Phase B: eliminate col k+1 wrt pivot1, find pivot2
        if (wid == 0 || wid == 1) {
            float* f1  = wid ? f1b : f1a;
            float* f2r = wid ? f2rb : f2ra;
            float* f2e = wid ? f2eb : f2ea;
            int* used  = wid ? usedb : useda;
            int p1     = wid ? sp1b : sp1a;
            float ip1  = wid ? sip1b : sip1a;
            float rn12 = f2r[p1] * ip1;
            float e0 = f2r[lane]      - f1[lane]      * rn12;
            float e1 = f2r[lane + 32] - f1[lane + 32] * rn12;
            if (lane == p1)      e0 = rn12;
            if (lane + 32 == p1) e1 = rn12;
            f2e[lane] = e0;
            f2e[lane + 32] = e1;
            float v0 = used[lane]      ? -1.0f : fabsf(e0);
            float v1 = used[lane + 32] ? -1.0f : fabsf(e1);
            int bi; float best, bv;
            if (v1 > v0) { best = v1; bi = lane + 32; bv = e1; }
            else         { best = v0; bi = lane;      bv = e0; }
            #pragma unroll
            for (int o = 16; o > 0; o >>= 1) {
                float ob = __shfl_down_sync(0xffffffffu, best, o);
                int   oi = __shfl_down_sync(0xffffffffu, bi, o);
                float ov = __shfl_down_sync(0xffffffffu, bv, o);
                if (ob > best) { best = ob; bi = oi; bv = ov; }
            }
            if (lane == 0) {
                used[bi] = 1;
                if (wid == 0) { sp2a = bi; pivka[k + 1] = bi; sip2a = 1.0f / bv; }
                else          { sp2b = bi; pivkb[k + 1] = bi; sip2b = 1.0f / bv; }
            }
        }
        __syncthreads();

        // Phase C: rank-2 updates, both batches
        {
            int p1 = sp1a, p2 = sp2a;
            float rn1 = aug0[j * ILD + p1] * sip1a;
            float rn2 = (aug0[j * ILD + p2] - f1a[p2] * rn1) * sip2a;
            if (rn1 != 0.0f || rn2 != 0.0f) {
                #pragma unroll
                for (int i4 = 0; i4 < M_; i4 += 4) {
                    float4 a  = *(const float4*)&f1a[i4];
                    float4 c2 = *(const float4*)&f2ea[i4];
                    float4 v  = *(const float4*)&aug0[j * ILD + i4];
                    v.x -= a.x * rn1 + c2.x * rn2;
                    v.y -= a.y * rn1 + c2.y * rn2;
                    v.z -= a.z * rn1 + c2.z * rn2;
                    v.w -= a.w * rn1 + c2.w * rn2;
                    *(float4*)&aug0[j * ILD + i4] = v;
                }
                aug0[j * ILD + p1] = rn1 - f2ea[p1] * rn2;
                aug0[j * ILD + p2] = rn2;
            }
        }
        {
            int p1 = sp1b, p2 = sp2b;
            float rn1 = aug1[j * ILD + p1] * sip1b;
            float rn2 = (aug1[j * ILD + p2] - f1b[p2] * rn1) * sip2b;
            if (rn1 != 0.0f || rn2 != 0.0f) {
                #pragma unroll
                for (int i4 = 0; i4 < M_; i4 += 4) {
                    float4 a  = *(const float4*)&f1b[i4];
                    float4 c2 = *(const float4*)&f2eb[i4];
                    float4 v  = *(const float4*)&aug1[j * ILD + i4];
                    v.x -= a.x * rn1 + c2.x * rn2;
                    v.y -= a.y * rn1 + c2.y * rn2;
                    v.z -= a.z * rn1 + c2.z * rn2;
                    v.w -= a.w * rn1 + c2.w * rn2;
                    *(float4*)&aug1[j * ILD + i4] = v;
                }
                aug1[j * ILD + p1] = rn1 - f2eb[p1] * rn2;
                aug1[j * ILD + p2] = rn2;
            }
        }
        __syncthreads();
    }

    // extract both batches
    for (int idx = tid; idx < M_ * M_; idx += 128) {
        int kk = idx >> 6, c = idx & 63;
        float v0 = aug0[(64 + c) * ILD + pivka[kk]];
        float v1 = aug1[(64 + c) * ILD + pivkb[kk]];
        g_S[(size_t)bb * 4096 + idx] = v0;
        g_S[(size_t)(bb + 1) * 4096 + idx] = v1;
        __nv_bfloat16 h0 = __float2bfloat16(v0);
        __nv_bfloat16 h1 = __float2bfloat16(v1);
        g_Whi[(size_t)bb * 8192 + (size_t)(64 + kk) * 64 + c] = h0;
        g_Wlo[(size_t)bb * 8192 + (size_t)(64 + kk) * 64 + c] =
            __float2bfloat16(v0 - __bfloat162float(h0));
        g_Whi[(size_t)(bb + 1) * 8192 + (size_t)(64 + kk) * 64 + c] = h1;
        g_Wlo[(size_t)(bb + 1) * 8192 + (size_t)(64 + kk) * 64 + c] =
            __float2bfloat16(v1 - __bfloat162float(h1));
    }
}

// ---------------- fused 64x64x64 x2: Tmp = S@C (smem), M = Tmp@S -> W rows 0..63 ----------------
#define MMLDS (M_ * 65)
#define MMSMEM ((MMLDS * 2 + M_ * M_) * 4)
__global__ void __launch_bounds__(256) k_mm64_fused() {
    extern __shared__ float sm[];
    float* sS = sm;
    float* sT = sm + MMLDS;
    float* sC = sm + MMLDS * 2;
    int b = blockIdx.x, tid = threadIdx.x;
    const float* S = g_S + (size_t)b * 4096;
    const float* C = g_C + (size_t)b * 4096;
    for (int i = tid; i < 4096; i += 256) {
        int r = i >> 6, c = i & 63;
        sS[r * 65 + c] = S[i];
        sC[i] = C[i];
    }
    __syncthreads();
    int tx = tid & 15, ty = tid >> 4;
    {
        float acc[4][4] = {};
        #pragma unroll 4
        for (int k = 0; k < M_; k++) {
            float xm[4], yn[4];
            #pragma unroll
            for (int i = 0; i < 4; i++) xm[i] = sS[(ty * 4 + i) * 65 + k];
            #pragma unroll
            for (int jj = 0; jj < 4; jj++) yn[jj] = sC[k * 64 + tx * 4 + jj];
            #pragma unroll
            for (int i = 0; i < 4; i++)
                #pragma unroll
                for (int jj = 0; jj < 4; jj++) acc[i][jj] += xm[i] * yn[jj];
        }
        #pragma unroll
        for (int i = 0; i < 4; i++)
            #pragma unroll
            for (int jj = 0; jj < 4; jj++)
                sT[(ty * 4 + i) * 65 + tx * 4 + jj] = acc[i][jj];
    }
    __syncthreads();
    {
        float acc[4][4] = {};
        #pragma unroll 4
        for (int k = 0; k < M_; k++) {
            float xm[4], yn[4];
            #pragma unroll
            for (int i = 0; i < 4; i++) xm[i] = sT[(ty * 4 + i) * 65 + k];
            #pragma unroll
            for (int jj = 0; jj < 4; jj++) yn[jj] = sS[k * 65 + tx * 4 + jj];
            #pragma unroll
            for (int i = 0; i < 4; i++)
                #pragma unroll
                for (int jj = 0; jj < 4; jj++) acc[i][jj] += xm[i] * yn[jj];
        }
        #pragma unroll
        for (int i = 0; i < 4; i++)
            #pragma unroll
            for (int jj = 0; jj < 4; jj++) {
                int r = ty * 4 + i, c = tx * 4 + jj;
                float v = acc[i][jj];
                __nv_bfloat16 h = __float2bfloat16(v);
                g_Whi[(size_t)b * 8192 + (size_t)r * 64 + c] = h;
                g_Wlo[(size_t)b * 8192 + (size_t)r * 64 + c] =
                    __float2bfloat16(v - __bfloat162float(h));
            }
    }
}

// ---------------- quadratic forms via mma.sync bf16 split, 128 grid cols/block ----------------
#define QNC 128
#define QLD 72
#define QOFF_WHI   0
#define QOFF_WLO   (QOFF_WHI + 128 * QLD * 2)
#define QOFF_BHI   (QOFF_WLO + 128 * QLD * 2)
#define QOFF_BLO   (QOFF_BHI + QNC * QLD * 2)
#define QOFF_SPART (QOFF_BLO + QNC * QLD * 2)
#define QSMEM_TOTAL (QOFF_SPART + 8 * QNC * 4)

__device__ __forceinline__ void mma16816(float d[4], const uint32_t a[4], const uint32_t b[2]) {
    asm volatile(
        "mma.sync.aligned.m16n8k16.row.col.f32.bf16.bf16.f32 "
        "{%0,%1,%2,%3}, {%4,%5,%6,%7}, {%8,%9}, {%0,%1,%2,%3};"
        : "+f"(d[0]), "+f"(d[1]), "+f"(d[2]), "+f"(d[3])
        : "r"(a[0]), "r"(a[1]), "r"(a[2]), "r"(a[3]), "r"(b[0]), "r"(b[1]));
}

__global__ void __launch_bounds__(256) k_quad_mma(const float* __restrict__ A) {
    extern __shared__ char smem[];
    __nv_bfloat16* sWhi = (__nv_bfloat16*)(smem + QOFF_WHI);
    __nv_bfloat16* sWlo = (__nv_bfloat16*)(smem + QOFF_WLO);
    __nv_bfloat16* sBhi = (__nv_bfloat16*)(smem + QOFF_BHI);
    __nv_bfloat16* sBlo = (__nv_bfloat16*)(smem + QOFF_BLO);
    float* spart = (float*)(smem + QOFF_SPART);

    int tid = threadIdx.x;
    int wid = tid >> 5, lane = tid & 31;
    int g0 = blockIdx.x * QNC;
    int b  = blockIdx.y;

    {
        const uint4* srcH = (const uint4*)(g_Whi + (size_t)b * 8192);
        const uint4* srcL = (const uint4*)(g_Wlo + (size_t)b * 8192);
        for (int i = tid; i < 1024; i += 256) {
            int r = i >> 3, c = i & 7;
            *(uint4*)&sWhi[r * QLD + c * 8] = srcH[i];
            *(uint4*)&sWlo[r * QLD + c * 8] = srcL[i];
        }
    }
    for (int i = tid; i < M_ * QNC; i += 256) {
        int k = i >> 7, g = i & (QNC - 1);
        float x = A[(size_t)k * G_ + g0 + g];
        __nv_bfloat16 h = __float2bfloat16(x);
        sBhi[g * QLD + k] = h;
        sBlo[g * QLD + k] = __float2bfloat16(x - __bfloat162float(h));
    }
    __syncthreads();

    int wrow = wid * 16;
    int r0 = wrow + (lane >> 2);
    int cq = (lane & 3) * 2;

    float d[16][4];
    #pragma unroll
    for (int t = 0; t < 16; t++)
        #pragma unroll
        for (int j = 0; j < 4; j++) d[t][j] = 0.0f;

    #pragma unroll
    for (int sp = 0; sp < 3; sp++) {
        const __nv_bfloat16* Wsrc = (sp == 2) ? sWlo : sWhi;
        const __nv_bfloat16* Bsrc = (sp == 1) ? sBlo : sBhi;
        #pragma unroll
        for (int ks = 0; ks < 4; ks++) {
            int kb = ks * 16;
            uint32_t a[4];
            a[0] = *(const uint32_t*)&Wsrc[r0 * QLD + kb + cq];
            a[1] = *(const uint32_t*)&Wsrc[(r0 + 8) * QLD + kb + cq];
            a[2] = *(const uint32_t*)&Wsrc[r0 * QLD + kb + cq + 8];
            a[3] = *(const uint32_t*)&Wsrc[(r0 + 8) * QLD + kb + cq + 8];
            int n = lane >> 2;
            #pragma unroll
            for (int t = 0; t < 16; t++) {
                uint32_t bb[2];
                bb[0] = *(const uint32_t*)&Bsrc[(t * 8 + n) * QLD + kb + cq];
                bb[1] = *(const uint32_t*)&Bsrc[(t * 8 + n) * QLD + kb + cq + 8];
                mma16816(d[t], a, bb);
            }
        }
    }

    int mbase = wrow & 63;
    int m0 = mbase + (lane >> 2);
    #pragma unroll
    for (int t = 0; t < 16; t++) {
        int g = t * 8 + cq;
        float a00 = __bfloat162float(sBhi[g * QLD + m0])       + __bfloat162float(sBlo[g * QLD + m0]);
        float a10 = __bfloat162float(sBhi[g * QLD + m0 + 8])   + __bfloat162float(sBlo[g * QLD + m0 + 8]);
        float a01 = __bfloat162float(sBhi[(g + 1) * QLD + m0]) + __bfloat162float(sBlo[(g + 1) * QLD + m0]);
        float a11 = __bfloat162float(sBhi[(g + 1) * QLD + m0 + 8]) + __bfloat162float(sBlo[(g + 1) * QLD + m0 + 8]);
        float p0 = d[t][0] * a00 + d[t][2] * a10;
        float p1 = d[t][1] * a01 + d[t][3] * a11;
        #pragma unroll
        for (int o = 4; o < 32; o <<= 1) {
            p0 += __shfl_xor_sync(0xffffffffu, p0, o);
            p1 += __shfl_xor_sync(0xffffffffu, p1, o);
        }
        if (lane < 4) {
            spart[wid * QNC + g] = p0;
            spart[wid * QNC + g + 1] = p1;
        }
    }
    __syncthreads();
    if (tid < QNC) {
        int g = tid;
        float t1 = spart[g] + spart[QNC + g] + spart[2 * QNC + g] + spart[3 * QNC + g];
        float t2 = spart[4 * QNC + g] + spart[5 * QNC + g] + spart[6 * QNC + g] + spart[7 * QNC + g];
        g_T1[(size_t)b * G_ + g0 + g] = t1;
        g_T2[(size_t)b * G_ + g0 + g] = fabsf(t2);
    }
}

// ---------------- per-gridpoint MLP ----------------
__global__ void k_mlp(const float* __restrict__ W1, const float* __restrict__ B1,
                      const float* __restrict__ W2, const float* __restrict__ B2,
                      const float* __restrict__ W3, const float* __restrict__ B3,
                      int it, int last, float* __restrict__ out) {
    int g = blockIdx.x;
    int b = threadIdx.x;
    __shared__ float sW1[96], sB1[32], sW2[1024], sB2[32], sW3[32], sB3;
    size_t gidx = (size_t)it * G_ + g;
    const float* w1 = W1 + gidx * 96;
    const float* w2 = W2 + gidx * 1024;
    if (b < 96) sW1[b] = w1[b];
    if (b < 32) {
        sB1[b] = B1[gidx * 32 + b];
        sB2[b] = B2[gidx * 32 + b];
        sW3[b] = W3[gidx * 32 + b];
    }
    if (b == 0) sB3 = B3[gidx];
    for (int i = b; i < 1024; i += 128) sW2[i] = w2[i];
    __syncthreads();

    float x0 = g_T1[(size_t)b * G_ + g];
    float x1 = g_T2[(size_t)b * G_ + g];
    float x2 = g_g[(size_t)b * G_ + g];

    float h[HID_];
    #pragma unroll
    for (int j = 0; j < HID_; j++) {
        float v = x0 * sW1[j] + x1 * sW1[32 + j] + x2 * sW1[64 + j] + sB1[j];
        h[j] = fmaxf(v, 0.0f);
    }
    float h2[HID_];
    #pragma unroll
    for (int j = 0; j < HID_; j++) h2[j] = sB2[j];
    #pragma unroll
    for (int j = 0; j < HID_; j++) {
        float hv = h[j];
        #pragma unroll
        for (int k = 0; k < HID_; k++) h2[k] += hv * sW2[j * 32 + k];
    }
    float o = sB3;
    #pragma unroll
    for (int k = 0; k < HID_; k++) o += fmaxf(h2[k], 0.0f) * sW3[k];

    if (last) out[(size_t)b * G_ + g] = o;
    else      g_g[(size_t)b * G_ + g] = o;
}

// ---------------- launch ----------------
extern "C" void kernel_launch(void* const* d_in, const int* in_sizes, int n_in,
                              void* d_out, int out_size) {
    const float* data = (const float*)d_in[0];
    const float* A    = (const float*)d_in[1];
    const float* W1   = (const float*)d_in[2];
    const float* b1   = (const float*)d_in[3];
    const float* W2   = (const float*)d_in[4];
    const float* b2   = (const float*)d_in[5];
    const float* W3   = (const float*)d_in[6];
    const float* b3   = (const float*)d_in[7];
    float* out = (float*)d_out;

    static int smem_set = 0;
    if (!smem_set) {
        cudaFuncSetAttribute(k_quad_mma, cudaFuncAttributeMaxDynamicSharedMemorySize, QSMEM_TOTAL);
        cudaFuncSetAttribute(k_mm64_fused, cudaFuncAttributeMaxDynamicSharedMemorySize, MMSMEM);
        cudaFuncSetAttribute(k_inv2, cudaFuncAttributeMaxDynamicSharedMemorySize, ISMEM);
        smem_set = 1;
    }

    k_init<<<(B_ * G_ + 255) / 256, 256>>>();
    k_datacov<<<B_, 256>>>(data);
    for (int it = 0; it < 3; it++) {
        k_cov<<<dim3(B_, KSPLIT), 256>>>(A);
        k_inv2<<<B_ / 2, 128, ISMEM>>>();
        k_mm64_fused<<<B_, 256, MMSMEM>>>();
        k_quad_mma<<<dim3(G_ / QNC, B_), 256, QSMEM_TOTAL>>>(A);
        k_mlp<<<G_, 128>>>(W1, b1, W2, b2, W3, b3, it, it == 2 ? 1 : 0, out);
    }
}

// round 10
// speedup vs baseline: 1.4753x; 1.0257x over previous
#include <cuda_runtime.h>
#include <cuda_bf16.h>
#include <cstdint>
#include <math.h>

#define B_      128
#define G_      2048
#define M_      64
#define T_      128
#define HID_    32
#define KSPLIT  4

// ================= scratch (device globals) =================
__device__ float g_C[B_ * M_ * M_];
__device__ float g_covp[KSPLIT * B_ * M_ * M_];
__device__ float g_S[B_ * M_ * M_];
__device__ float g_T1[B_ * G_];
__device__ float g_T2[B_ * G_];
__device__ float g_g[B_ * G_];
// stacked W per batch: rows 0..63 = M = S C S, rows 64..127 = S; bf16 2-term split
__device__ __nv_bfloat16 g_Whi[B_ * 128 * 64];
__device__ __nv_bfloat16 g_Wlo[B_ * 128 * 64];

// ---------------- init gamma = 1 ----------------
__global__ void k_init() {
    int i = blockIdx.x * blockDim.x + threadIdx.x;
    if (i < B_ * G_) g_g[i] = 1.0f;
}

// ---------------- C_b = data_b data_b^T / T (once) ----------------
__global__ void k_datacov(const float* __restrict__ data) {
    __shared__ float sh[M_][T_ + 1];
    int b = blockIdx.x;
    const float* d = data + (size_t)b * M_ * T_;
    for (int i = threadIdx.x; i < M_ * T_; i += blockDim.x)
        sh[i >> 7][i & 127] = d[i];
    __syncthreads();
    for (int idx = threadIdx.x; idx < M_ * M_; idx += blockDim.x) {
        int m = idx >> 6, n = idx & 63;
        float acc = 0.f;
        #pragma unroll 8
        for (int t = 0; t < T_; t++) acc += sh[m][t] * sh[n][t];
        g_C[(size_t)b * 4096 + idx] = acc * (1.0f / (float)T_);
    }
}

// ---------------- cov partial (triangular, fp32 SIMT — known good) ----------------
__global__ void __launch_bounds__(256) k_cov(const float* __restrict__ A) {
    __shared__ float shA[M_][33];
    __shared__ float shg[32];
    int b = blockIdx.x;
    int ks = blockIdx.y;
    int tid = threadIdx.x;

    bool act = tid < 136;
    int ty = 0, tx = 0;
    if (act) {
        float ft = (sqrtf(8.0f * (float)tid + 1.0f) - 1.0f) * 0.5f;
        ty = (int)ft;
        if ((ty + 1) * (ty + 2) / 2 <= tid) ty++;
        if (ty * (ty + 1) / 2 > tid) ty--;
        tx = tid - ty * (ty + 1) / 2;
    }

    float acc[4][4] = {};
    int kbeg = ks * (G_ / KSPLIT), kend = kbeg + (G_ / KSPLIT);
    for (int k0 = kbeg; k0 < kend; k0 += 32) {
        for (int i = tid; i < M_ * 32; i += 256) {
            int r = i >> 5, c = i & 31;
            shA[r][c] = A[(size_t)r * G_ + k0 + c];
        }
        if (tid < 32) shg[tid] = g_g[(size_t)b * G_ + k0 + tid];
        __syncthreads();
        if (act) {
            #pragma unroll 4
            for (int k = 0; k < 32; k++) {
                float gv = shg[k];
                float am[4], an[4];
                #pragma unroll
                for (int i = 0; i < 4; i++) am[i] = shA[ty * 4 + i][k] * gv;
                #pragma unroll
                for (int j = 0; j < 4; j++) an[j] = shA[tx * 4 + j][k];
                #pragma unroll
                for (int i = 0; i < 4; i++)
                    #pragma unroll
                    for (int j = 0; j < 4; j++) acc[i][j] += am[i] * an[j];
            }
        }
        __syncthreads();
    }
    if (act) {
        float* dst = g_covp + ((size_t)ks * B_ + b) * 4096;
        #pragma unroll
        for (int i = 0; i < 4; i++)
            #pragma unroll
            for (int j = 0; j < 4; j++) {
                dst[(ty * 4 + i) * 64 + tx * 4 + j] = acc[i][j];
                dst[(tx * 4 + j) * 64 + ty * 4 + i] = acc[i][j];
            }
    }
}

// ---------------- Gauss-Jordan inverse, panel-2 (R5 proven, 47us) ----------------
#define ILD 68
__global__ void __launch_bounds__(128) k_inv() {
    __shared__ float augT[128][ILD];                 // [column][row]
    __shared__ __align__(16) float f1[M_];
    __shared__ __align__(16) float f2e[M_];
    __shared__ __align__(16) float f2r[M_];
    __shared__ int s_p1, s_p2;
    __shared__ float s_ip1, s_ip2;
    __shared__ int pivk[M_];
    __shared__ int used[M_];
    int b = blockIdx.x, tid = threadIdx.x;
    int wid = tid >> 5, lane = tid & 31;
    int j = tid;

    for (int idx = tid; idx < M_ * M_; idx += 128) {
        int i = idx >> 6, c = idx & 63;
        float v = g_covp[(size_t)b * 4096 + idx]
                + g_covp[(size_t)(B_ + b) * 4096 + idx]
                + g_covp[(size_t)(2 * B_ + b) * 4096 + idx]
                + g_covp[(size_t)(3 * B_ + b) * 4096 + idx];
        if (i == c) v += 0.1f;
        augT[c][i] = v;
        augT[64 + c][i] = (i == c) ? 1.0f : 0.0f;
    }
    if (tid < M_) used[tid] = 0;
    __syncthreads();

    for (int k = 0; k < M_; k += 2) {
        if (wid == 0) {
            float sv0 = augT[k][lane], sv1 = augT[k][lane + 32];
            float v0 = used[lane]      ? -1.0f : fabsf(sv0);
            float v1 = used[lane + 32] ? -1.0f : fabsf(sv1);
            int bi; float best, bv;
            if (v1 > v0) { best = v1; bi = lane + 32; bv = sv1; }
            else         { best = v0; bi = lane;      bv = sv0; }
            #pragma unroll
            for (int o = 16; o > 0; o >>= 1) {
                float ob = __shfl_down_sync(0xffffffffu, best, o);
                int   oi = __shfl_down_sync(0xffffffffu, bi, o);
                float ov = __shfl_down_sync(0xffffffffu, bv, o);
                if (ob > best) { best = ob; bi = oi; bv = ov; }
            }
            if (lane == 0) {
                s_p1 = bi; used[bi] = 1; pivk[k] = bi;
                s_ip1 = 1.0f / bv;
            }
        } else if (wid == 1) {
            f1[lane] = augT[k][lane];
            f1[lane + 32] = augT[k][lane + 32];
        } else if (wid == 2) {
            f2r[lane] = augT[k + 1][lane];
            f2r[lane + 32] = augT[k + 1][lane + 32];
        }
        __syncthreads();

        if (wid == 0) {
            int p1 = s_p1; float ip1 = s_ip1;
            float rn12 = f2r[p1] * ip1;
            float e0 = f2r[lane]      - f1[lane]      * rn12;
            float e1 = f2r[lane + 32] - f1[lane + 32] * rn12;
            if (lane == p1)      e0 = rn12;
            if (lane + 32 == p1) e1 = rn12;
            f2e[lane] = e0;
            f2e[lane + 32] = e1;
            float v0 = used[lane]      ? -1.0f : fabsf(e0);
            float v1 = used[lane + 32] ? -1.0f : fabsf(e1);
            int bi; float best, bv;
            if (v1 > v0) { best = v1; bi = lane + 32; bv = e1; }
            else         { best = v0; bi = lane;      bv = e0; }
            #pragma unroll
            for (int o = 16; o > 0; o >>= 1) {
                float ob = __shfl_down_sync(0xffffffffu, best, o);
                int   oi = __shfl_down_sync(0xffffffffu, bi, o);
                float ov = __shfl_down_sync(0xffffffffu, bv, o);
                if (ob > best) { best = ob; bi = oi; bv = ov; }
            }
            if (lane == 0) {
                s_p2 = bi; used[bi] = 1; pivk[k + 1] = bi;
                s_ip2 = 1.0f / bv;
            }
        }
        __syncthreads();

        {
            int p1 = s_p1, p2 = s_p2;
            float ip1 = s_ip1, ip2 = s_ip2;
            float rn1 = augT[j][p1] * ip1;
            float rn2 = (augT[j][p2] - f1[p2] * rn1) * ip2;
            if (rn1 != 0.0f || rn2 != 0.0f) {
                #pragma unroll
                for (int i4 = 0; i4 < M_; i4 += 4) {
                    float4 a  = *(const float4*)&f1[i4];
                    float4 c2 = *(const float4*)&f2e[i4];
                    float4 v  = *(const float4*)&augT[j][i4];
                    v.x -= a.x * rn1 + c2.x * rn2;
                    v.y -= a.y * rn1 + c2.y * rn2;
                    v.z -= a.z * rn1 + c2.z * rn2;
                    v.w -= a.w * rn1 + c2.w * rn2;
                    *(float4*)&augT[j][i4] = v;
                }
                augT[j][p1] = rn1 - f2e[p1] * rn2;
                augT[j][p2] = rn2;
            }
        }
        __syncthreads();
    }

    for (int idx = tid; idx < M_ * M_; idx += 128) {
        int kk = idx >> 6, c = idx & 63;
        float v = augT[64 + c][pivk[kk]];
        g_S[(size_t)b * 4096 + idx] = v;
        __nv_bfloat16 h = __float2bfloat16(v);
        g_Whi[(size_t)b * 8192 + (size_t)(64 + kk) * 64 + c] = h;
        g_Wlo[(size_t)b * 8192 + (size_t)(64 + kk) * 64 + c] =
            __float2bfloat16(v - __bfloat162float(h));
    }
}

// ---------------- fused 64x64x64 x2: Tmp = S@C (smem), M = Tmp@S -> W rows 0..63 ----------------
#define MMLDS (M_ * 65)
#define MMSMEM ((MMLDS * 2 + M_ * M_) * 4)
__global__ void __launch_bounds__(256) k_mm64_fused() {
    extern __shared__ float sm[];
    float* sS = sm;
    float* sT = sm + MMLDS;
    float* sC = sm + MMLDS * 2;
    int b = blockIdx.x, tid = threadIdx.x;
    const float* S = g_S + (size_t)b * 4096;
    const float* C = g_C + (size_t)b * 4096;
    for (int i = tid; i < 4096; i += 256) {
        int r = i >> 6, c = i & 63;
        sS[r * 65 + c] = S[i];
        sC[i] = C[i];
    }
    __syncthreads();
    int tx = tid & 15, ty = tid >> 4;
    {
        float acc[4][4] = {};
        #pragma unroll 4
        for (int k = 0; k < M_; k++) {
            float xm[4], yn[4];
            #pragma unroll
            for (int i = 0; i < 4; i++) xm[i] = sS[(ty * 4 + i) * 65 + k];
            #pragma unroll
            for (int jj = 0; jj < 4; jj++) yn[jj] = sC[k * 64 + tx * 4 + jj];
            #pragma unroll
            for (int i = 0; i < 4; i++)
                #pragma unroll
                for (int jj = 0; jj < 4; jj++) acc[i][jj] += xm[i] * yn[jj];
        }
        #pragma unroll
        for (int i = 0; i < 4; i++)
            #pragma unroll
            for (int jj = 0; jj < 4; jj++)
                sT[(ty * 4 + i) * 65 + tx * 4 + jj] = acc[i][jj];
    }
    __syncthreads();
    {
        float acc[4][4] = {};
        #pragma unroll 4
        for (int k = 0; k < M_; k++) {
            float xm[4], yn[4];
            #pragma unroll
            for (int i = 0; i < 4; i++) xm[i] = sT[(ty * 4 + i) * 65 + k];
            #pragma unroll
            for (int jj = 0; jj < 4; jj++) yn[jj] = sS[k * 65 + tx * 4 + jj];
            #pragma unroll
            for (int i = 0; i < 4; i++)
                #pragma unroll
                for (int jj = 0; jj < 4; jj++) acc[i][jj] += xm[i] * yn[jj];
        }
        #pragma unroll
        for (int i = 0; i < 4; i++)
            #pragma unroll
            for (int jj = 0; jj < 4; jj++) {
                int r = ty * 4 + i, c = tx * 4 + jj;
                float v = acc[i][jj];
                __nv_bfloat16 h = __float2bfloat16(v);
                g_Whi[(size_t)b * 8192 + (size_t)r * 64 + c] = h;
                g_Wlo[(size_t)b * 8192 + (size_t)r * 64 + c] =
                    __float2bfloat16(v - __bfloat162float(h));
            }
    }
}

// ---------------- quadratic forms via mma.sync bf16 split, 4x2 warp tiling ----------------
#define QNC 128
#define QLD 72
#define QOFF_WHI   0
#define QOFF_WLO   (QOFF_WHI + 128 * QLD * 2)
#define QOFF_BHI   (QOFF_WLO + 128 * QLD * 2)
#define QOFF_BLO   (QOFF_BHI + QNC * QLD * 2)
#define QOFF_SPART (QOFF_BLO + QNC * QLD * 2)
#define QSMEM_TOTAL (QOFF_SPART + 4 * QNC * 4)

__device__ __forceinline__ void mma16816(float d[4], const uint32_t a[4], const uint32_t b[2]) {
    asm volatile(
        "mma.sync.aligned.m16n8k16.row.col.f32.bf16.bf16.f32 "
        "{%0,%1,%2,%3}, {%4,%5,%6,%7}, {%8,%9}, {%0,%1,%2,%3};"
        : "+f"(d[0]), "+f"(d[1]), "+f"(d[2]), "+f"(d[3])
        : "r"(a[0]), "r"(a[1]), "r"(a[2]), "r"(a[3]), "r"(b[0]), "r"(b[1]));
}

__global__ void __launch_bounds__(256) k_quad_mma(const float* __restrict__ A) {
    extern __shared__ char smem[];
    __nv_bfloat16* sWhi = (__nv_bfloat16*)(smem + QOFF_WHI);
    __nv_bfloat16* sWlo = (__nv_bfloat16*)(smem + QOFF_WLO);
    __nv_bfloat16* sBhi = (__nv_bfloat16*)(smem + QOFF_BHI);
    __nv_bfloat16* sBlo = (__nv_bfloat16*)(smem + QOFF_BLO);
    float* spart = (float*)(smem + QOFF_SPART);

    int tid = threadIdx.x;
    int wid = tid >> 5, lane = tid & 31;
    int wm = wid & 3;          // W-row group: rows [wm*32, wm*32+32)
    int wn = wid >> 2;         // g group: cols [wn*64, wn*64+64)
    int g0 = blockIdx.x * QNC;
    int b  = blockIdx.y;

    {
        const uint4* srcH = (const uint4*)(g_Whi + (size_t)b * 8192);
        const uint4* srcL = (const uint4*)(g_Wlo + (size_t)b * 8192);
        for (int i = tid; i < 1024; i += 256) {
            int r = i >> 3, c = i & 7;
            *(uint4*)&sWhi[r * QLD + c * 8] = srcH[i];
            *(uint4*)&sWlo[r * QLD + c * 8] = srcL[i];
        }
    }
    for (int i = tid; i < M_ * QNC; i += 256) {
        int k = i >> 7, g = i & (QNC - 1);
        float x = A[(size_t)k * G_ + g0 + g];
        __nv_bfloat16 h = __float2bfloat16(x);
        sBhi[g * QLD + k] = h;
        sBlo[g * QLD + k] = __float2bfloat16(x - __bfloat162float(h));
    }
    __syncthreads();

    int lr = lane >> 2;
    int cq = (lane & 3) * 2;

    float d[2][8][4];
    #pragma unroll
    for (int f = 0; f < 2; f++)
        #pragma unroll
        for (int t = 0; t < 8; t++)
            #pragma unroll
            for (int q = 0; q < 4; q++) d[f][t][q] = 0.0f;

    #pragma unroll
    for (int sp = 0; sp < 3; sp++) {
        const __nv_bfloat16* Wsrc = (sp == 2) ? sWlo : sWhi;
        const __nv_bfloat16* Bsrc = (sp == 1) ? sBlo : sBhi;
        #pragma unroll
        for (int ks = 0; ks < 4; ks++) {
            int kb = ks * 16;
            uint32_t a[2][4];
            #pragma unroll
            for (int f = 0; f < 2; f++) {
                int r0 = wm * 32 + f * 16 + lr;
                a[f][0] = *(const uint32_t*)&Wsrc[r0 * QLD + kb + cq];
                a[f][1] = *(const uint32_t*)&Wsrc[(r0 + 8) * QLD + kb + cq];
                a[f][2] = *(const uint32_t*)&Wsrc[r0 * QLD + kb + cq + 8];
                a[f][3] = *(const uint32_t*)&Wsrc[(r0 + 8) * QLD + kb + cq + 8];
            }
            #pragma unroll
            for (int t = 0; t < 8; t++) {
                int gl = wn * 64 + t * 8 + lr;
                uint32_t bb[2];
                bb[0] = *(const uint32_t*)&Bsrc[gl * QLD + kb + cq];
                bb[1] = *(const uint32_t*)&Bsrc[gl * QLD + kb + cq + 8];
                mma16816(d[0][t], a[0], bb);
                mma16816(d[1][t], a[1], bb);
            }
        }
    }

    // epilogue: p[g] = sum over this warp's 32 W-rows of A[m&63, g] * V[m, g]
    #pragma unroll
    for (int t = 0; t < 8; t++) {
        int gcol = wn * 64 + t * 8 + cq;
        float p0 = 0.0f, p1 = 0.0f;
        #pragma unroll
        for (int f = 0; f < 2; f++) {
            int m0 = (wm * 32 + f * 16 + lr) & 63;
            int m8 = m0 + 8;
            float a00 = __bfloat162float(sBhi[gcol * QLD + m0]) + __bfloat162float(sBlo[gcol * QLD + m0]);
            float a10 = __bfloat162float(sBhi[gcol * QLD + m8]) + __bfloat162float(sBlo[gcol * QLD + m8]);
            float a01 = __bfloat162float(sBhi[(gcol + 1) * QLD + m0]) + __bfloat162float(sBlo[(gcol + 1) * QLD + m0]);
            float a11 = __bfloat162float(sBhi[(gcol + 1) * QLD + m8]) + __bfloat162float(sBlo[(gcol + 1) * QLD + m8]);
            p0 += d[f][t][0] * a00 + d[f][t][2] * a10;
            p1 += d[f][t][1] * a01 + d[f][t][3] * a11;
        }
        #pragma unroll
        for (int o = 4; o < 32; o <<= 1) {
            p0 += __shfl_xor_sync(0xffffffffu, p0, o);
            p1 += __shfl_xor_sync(0xffffffffu, p1, o);
        }
        if (lane < 4) {
            spart[wm * QNC + gcol] = p0;
            spart[wm * QNC + gcol + 1] = p1;
        }
    }
    __syncthreads();
    if (tid < QNC) {
        int g = tid;
        float t1 = spart[g] + spart[QNC + g];
        float t2 = spart[2 * QNC + g] + spart[3 * QNC + g];
        g_T1[(size_t)b * G_ + g0 + g] = t1;
        g_T2[(size_t)b * G_ + g0 + g] = fabsf(t2);
    }
}

// ---------------- per-gridpoint MLP ----------------
__global__ void k_mlp(const float* __restrict__ W1, const float* __restrict__ B1,
                      const float* __restrict__ W2, const float* __restrict__ B2,
                      const float* __restrict__ W3, const float* __restrict__ B3,
                      int it, int last, float* __restrict__ out) {
    int g = blockIdx.x;
    int b = threadIdx.x;
    __shared__ float sW1[96], sB1[32], sW2[1024], sB2[32], sW3[32], sB3;
    size_t gidx = (size_t)it * G_ + g;
    const float* w1 = W1 + gidx * 96;
    const float* w2 = W2 + gidx * 1024;
    if (b < 96) sW1[b] = w1[b];
    if (b < 32) {
        sB1[b] = B1[gidx * 32 + b];
        sB2[b] = B2[gidx * 32 + b];
        sW3[b] = W3[gidx * 32 + b];
    }
    if (b == 0) sB3 = B3[gidx];
    for (int i = b; i < 1024; i += 128) sW2[i] = w2[i];
    __syncthreads();

    float x0 = g_T1[(size_t)b * G_ + g];
    float x1 = g_T2[(size_t)b * G_ + g];
    float x2 = g_g[(size_t)b * G_ + g];

    float h[HID_];
    #pragma unroll
    for (int j = 0; j < HID_; j++) {
        float v = x0 * sW1[j] + x1 * sW1[32 + j] + x2 * sW1[64 + j] + sB1[j];
        h[j] = fmaxf(v, 0.0f);
    }
    float h2[HID_];
    #pragma unroll
    for (int j = 0; j < HID_; j++) h2[j] = sB2[j];
    #pragma unroll
    for (int j = 0; j < HID_; j++) {
        float hv = h[j];
        #pragma unroll
        for (int k = 0; k < HID_; k++) h2[k] += hv * sW2[j * 32 + k];
    }
    float o = sB3;
    #pragma unroll
    for (int k = 0; k < HID_; k++) o += fmaxf(h2[k], 0.0f) * sW3[k];

    if (last) out[(size_t)b * G_ + g] = o;
    else      g_g[(size_t)b * G_ + g] = o;
}

// ---------------- launch ----------------
extern "C" void kernel_launch(void* const* d_in, const int* in_sizes, int n_in,
                              void* d_out, int out_size) {
    const float* data = (const float*)d_in[0];
    const float* A    = (const float*)d_in[1];
    const float* W1   = (const float*)d_in[2];
    const float* b1   = (const float*)d_in[3];
    const float* W2   = (const float*)d_in[4];
    const float* b2   = (const float*)d_in[5];
    const float* W3   = (const float*)d_in[6];
    const float* b3   = (const float*)d_in[7];
    float* out = (float*)d_out;

    static int smem_set = 0;
    if (!smem_set) {
        cudaFuncSetAttribute(k_quad_mma, cudaFuncAttributeMaxDynamicSharedMemorySize, QSMEM_TOTAL);
        cudaFuncSetAttribute(k_mm64_fused, cudaFuncAttributeMaxDynamicSharedMemorySize, MMSMEM);
        smem_set = 1;
    }

    k_init<<<(B_ * G_ + 255) / 256, 256>>>();
    k_datacov<<<B_, 256>>>(data);
    for (int it = 0; it < 3; it++) {
        k_cov<<<dim3(B_, KSPLIT), 256>>>(A);
        k_inv<<<B_, 128>>>();
        k_mm64_fused<<<B_, 256, MMSMEM>>>();
        k_quad_mma<<<dim3(G_ / QNC, B_), 256, QSMEM_TOTAL>>>(A);
        k_mlp<<<G_, 128>>>(W1, b1, W2, b2, W3, b3, it, it == 2 ? 1 : 0, out);
    }
}

// round 11
// speedup vs baseline: 1.5097x; 1.0234x over previous
#include <cuda_runtime.h>
#include <cuda_bf16.h>
#include <cstdint>
#include <math.h>

#define B_      128
#define G_      2048
#define M_      64
#define T_      128
#define HID_    32
#define KSPLIT  4

// ================= scratch (device globals) =================
__device__ float g_C[B_ * M_ * M_];
__device__ float g_covp[KSPLIT * B_ * M_ * M_];
__device__ float g_S[B_ * M_ * M_];
__device__ float g_T1[B_ * G_];
__device__ float g_T2[B_ * G_];
__device__ float g_g[B_ * G_];
// stacked W per batch: rows 0..63 = M = S C S, rows 64..127 = S; bf16 2-term split
__device__ __nv_bfloat16 g_Whi[B_ * 128 * 64];
__device__ __nv_bfloat16 g_Wlo[B_ * 128 * 64];

// ---------------- init gamma = 1 ----------------
__global__ void k_init() {
    int i = blockIdx.x * blockDim.x + threadIdx.x;
    if (i < B_ * G_) g_g[i] = 1.0f;
}

// ---------------- C_b = data_b data_b^T / T (once) ----------------
__global__ void k_datacov(const float* __restrict__ data) {
    __shared__ float sh[M_][T_ + 1];
    int b = blockIdx.x;
    const float* d = data + (size_t)b * M_ * T_;
    for (int i = threadIdx.x; i < M_ * T_; i += blockDim.x)
        sh[i >> 7][i & 127] = d[i];
    __syncthreads();
    for (int idx = threadIdx.x; idx < M_ * M_; idx += blockDim.x) {
        int m = idx >> 6, n = idx & 63;
        float acc = 0.f;
        #pragma unroll 8
        for (int t = 0; t < T_; t++) acc += sh[m][t] * sh[n][t];
        g_C[(size_t)b * 4096 + idx] = acc * (1.0f / (float)T_);
    }
}

// ---------------- cov partial (triangular, fp32 SIMT — known good) ----------------
__global__ void __launch_bounds__(256) k_cov(const float* __restrict__ A) {
    __shared__ float shA[M_][33];
    __shared__ float shg[32];
    int b = blockIdx.x;
    int ks = blockIdx.y;
    int tid = threadIdx.x;

    bool act = tid < 136;
    int ty = 0, tx = 0;
    if (act) {
        float ft = (sqrtf(8.0f * (float)tid + 1.0f) - 1.0f) * 0.5f;
        ty = (int)ft;
        if ((ty + 1) * (ty + 2) / 2 <= tid) ty++;
        if (ty * (ty + 1) / 2 > tid) ty--;
        tx = tid - ty * (ty + 1) / 2;
    }

    float acc[4][4] = {};
    int kbeg = ks * (G_ / KSPLIT), kend = kbeg + (G_ / KSPLIT);
    for (int k0 = kbeg; k0 < kend; k0 += 32) {
        for (int i = tid; i < M_ * 32; i += 256) {
            int r = i >> 5, c = i & 31;
            shA[r][c] = A[(size_t)r * G_ + k0 + c];
        }
        if (tid < 32) shg[tid] = g_g[(size_t)b * G_ + k0 + tid];
        __syncthreads();
        if (act) {
            #pragma unroll 4
            for (int k = 0; k < 32; k++) {
                float gv = shg[k];
                float am[4], an[4];
                #pragma unroll
                for (int i = 0; i < 4; i++) am[i] = shA[ty * 4 + i][k] * gv;
                #pragma unroll
                for (int j = 0; j < 4; j++) an[j] = shA[tx * 4 + j][k];
                #pragma unroll
                for (int i = 0; i < 4; i++)
                    #pragma unroll
                    for (int j = 0; j < 4; j++) acc[i][j] += am[i] * an[j];
            }
        }
        __syncthreads();
    }
    if (act) {
        float* dst = g_covp + ((size_t)ks * B_ + b) * 4096;
        #pragma unroll
        for (int i = 0; i < 4; i++)
            #pragma unroll
            for (int j = 0; j < 4; j++) {
                dst[(ty * 4 + i) * 64 + tx * 4 + j] = acc[i][j];
                dst[(tx * 4 + j) * 64 + ty * 4 + i] = acc[i][j];
            }
    }
}

// ---------------- Gauss-Jordan inverse, panel-4 (rank-4 updates) ----------------
#define ILD 68
// broadcast element p of a (v0=idx lane, v1=idx lane+32) register pair across warp
__device__ __forceinline__ float wpick(float v0, float v1, int p) {
    float a = __shfl_sync(0xffffffffu, v0, p & 31);
    float b = __shfl_sync(0xffffffffu, v1, p & 31);
    return (p < 32) ? a : b;
}
// masked butterfly argmax: every lane ends with (bi, bv) of the max |value|
__device__ __forceinline__ void wargmax(float e0, float e1, bool u0, bool u1,
                                        int lane, int& bi_out, float& bv_out) {
    float v0 = u0 ? fabsf(e0) : -1.0f;
    float v1 = u1 ? fabsf(e1) : -1.0f;
    int bi; float best, bv;
    if (v1 > v0) { best = v1; bi = lane + 32; bv = e1; }
    else         { best = v0; bi = lane;      bv = e0; }
    #pragma unroll
    for (int o = 16; o > 0; o >>= 1) {
        float ob = __shfl_xor_sync(0xffffffffu, best, o);
        int   oi = __shfl_xor_sync(0xffffffffu, bi, o);
        float ov = __shfl_xor_sync(0xffffffffu, bv, o);
        if (ob > best || (ob == best && oi < bi)) { best = ob; bi = oi; bv = ov; }
    }
    bi_out = bi; bv_out = bv;
}

__global__ void __launch_bounds__(128) k_inv() {
    __shared__ float augT[128][ILD];                 // [column][row]
    __shared__ __align__(16) float f1[M_], f2e[M_], f3e[M_], f4e[M_];
    __shared__ __align__(16) float f2r[M_], f3r[M_];
    __shared__ int s_p[4];
    __shared__ float s_ip[4];
    __shared__ int pivk[M_];
    int b = blockIdx.x, tid = threadIdx.x;
    int wid = tid >> 5, lane = tid & 31;
    int j = tid;

    for (int idx = tid; idx < M_ * M_; idx += 128) {
        int i = idx >> 6, c = idx & 63;
        float v = g_covp[(size_t)b * 4096 + idx]
                + g_covp[(size_t)(B_ + b) * 4096 + idx]
                + g_covp[(size_t)(2 * B_ + b) * 4096 + idx]
                + g_covp[(size_t)(3 * B_ + b) * 4096 + idx];
        if (i == c) v += 0.1f;
        augT[c][i] = v;
        augT[64 + c][i] = (i == c) ? 1.0f : 0.0f;
    }
    __syncthreads();

    // warp0-private unused flags (persistent across panels)
    bool u0 = true, u1 = true;

    for (int k = 0; k < M_; k += 4) {
        // -------- Phase A: pivot1 (warp0) || snapshots cols k,k+1,k+2 (warps 1..3)
        if (wid == 0) {
            float c0 = augT[k][lane], c1 = augT[k][lane + 32];
            int p1; float pv1;
            wargmax(c0, c1, u0, u1, lane, p1, pv1);
            if (p1 == lane) u0 = false;
            if (p1 == lane + 32) u1 = false;
            if (lane == 0) { s_p[0] = p1; s_ip[0] = 1.0f / pv1; pivk[k] = p1; }
        } else if (wid == 1) {
            f1[lane] = augT[k][lane];
            f1[lane + 32] = augT[k][lane + 32];
        } else if (wid == 2) {
            f2r[lane] = augT[k + 1][lane];
            f2r[lane + 32] = augT[k + 1][lane + 32];
        } else {
            f3r[lane] = augT[k + 2][lane];
            f3r[lane + 32] = augT[k + 2][lane + 32];
        }
        __syncthreads();

        // -------- Phase B (warp0 only): eliminate cols k+1..k+3, pick pivots 2..4
        if (wid == 0) {
            int p1 = s_p[0]; float ip1 = s_ip[0];
            float f1_0 = f1[lane], f1_1 = f1[lane + 32];

            // col k+1
            float g0 = f2r[lane], g1 = f2r[lane + 32];
            float rn12 = wpick(g0, g1, p1) * ip1;
            float e2_0 = g0 - f1_0 * rn12;
            float e2_1 = g1 - f1_1 * rn12;
            if (lane == p1)      e2_0 = rn12;
            if (lane + 32 == p1) e2_1 = rn12;
            int p2; float pv2;
            wargmax(e2_0, e2_1, u0, u1, lane, p2, pv2);
            if (p2 == lane) u0 = false;
            if (p2 == lane + 32) u1 = false;
            float ip2 = 1.0f / pv2;
            f2e[lane] = e2_0; f2e[lane + 32] = e2_1;

            // col k+2
            float h0 = f3r[lane], h1 = f3r[lane + 32];
            float rn13 = wpick(h0, h1, p1) * ip1;
            float rn23 = (wpick(h0, h1, p2) - wpick(f1_0, f1_1, p2) * rn13) * ip2;
            float e3_0 = h0 - f1_0 * rn13 - e2_0 * rn23;
            float e3_1 = h1 - f1_1 * rn13 - e2_1 * rn23;
            if (lane == p1)      e3_0 = rn13 - e2_0 * rn23;   // e2_0 at p1 == rn12
            if (lane + 32 == p1) e3_1 = rn13 - e2_1 * rn23;
            if (lane == p2)      e3_0 = rn23;
            if (lane + 32 == p2) e3_1 = rn23;
            int p3; float pv3;
            wargmax(e3_0, e3_1, u0, u1, lane, p3, pv3);
            if (p3 == lane) u0 = false;
            if (p3 == lane + 32) u1 = false;
            float ip3 = 1.0f / pv3;
            f3e[lane] = e3_0; f3e[lane + 32] = e3_1;

            // col k+3 (read directly; untouched so far)
            float q0 = augT[k + 3][lane], q1 = augT[k + 3][lane + 32];
            float rn14 = wpick(q0, q1, p1) * ip1;
            float rn24 = (wpick(q0, q1, p2) - wpick(f1_0, f1_1, p2) * rn14) * ip2;
            float rn34 = (wpick(q0, q1, p3) - wpick(f1_0, f1_1, p3) * rn14
                          - wpick(e2_0, e2_1, p3) * rn24) * ip3;
            float e4_0 = q0 - f1_0 * rn14 - e2_0 * rn24 - e3_0 * rn34;
            float e4_1 = q1 - f1_1 * rn14 - e2_1 * rn24 - e3_1 * rn34;
            if (lane == p1)      e4_0 = rn14 - e2_0 * rn24 - e3_0 * rn34;
            if (lane + 32 == p1) e4_1 = rn14 - e2_1 * rn24 - e3_1 * rn34;
            if (lane == p2)      e4_0 = rn24 - e3_0 * rn34;
            if (lane + 32 == p2) e4_1 = rn24 - e3_1 * rn34;
            if (lane == p3)      e4_0 = rn34;
            if (lane + 32 == p3) e4_1 = rn34;
            int p4; float pv4;
            wargmax(e4_0, e4_1, u0, u1, lane, p4, pv4);
            if (p4 == lane) u0 = false;
            if (p4 == lane + 32) u1 = false;
            f4e[lane] = e4_0; f4e[lane + 32] = e4_1;

            if (lane == 0) {
                s_p[1] = p2; s_ip[1] = ip2; pivk[k + 1] = p2;
                s_p[2] = p3; s_ip[2] = ip3; pivk[k + 2] = p3;
                s_p[3] = p4; s_ip[3] = 1.0f / pv4; pivk[k + 3] = p4;
            }
        }
        __syncthreads();

        // -------- Phase C: rank-4 update, all columns
        {
            int p1 = s_p[0], p2 = s_p[1], p3 = s_p[2], p4 = s_p[3];
            float ip1 = s_ip[0], ip2 = s_ip[1], ip3 = s_ip[2], ip4 = s_ip[3];
            float rn1 = augT[j][p1] * ip1;
            float rn2 = (augT[j][p2] - f1[p2] * rn1) * ip2;
            float rn3 = (augT[j][p3] - f1[p3] * rn1 - f2e[p3] * rn2) * ip3;
            float rn4 = (augT[j][p4] - f1[p4] * rn1 - f2e[p4] * rn2 - f3e[p4] * rn3) * ip4;
            if (rn1 != 0.0f || rn2 != 0.0f || rn3 != 0.0f || rn4 != 0.0f) {
                #pragma unroll
                for (int i4 = 0; i4 < M_; i4 += 4) {
                    float4 a1 = *(const float4*)&f1[i4];
                    float4 a2 = *(const float4*)&f2e[i4];
                    float4 a3 = *(const float4*)&f3e[i4];
                    float4 a4 = *(const float4*)&f4e[i4];
                    float4 v  = *(const float4*)&augT[j][i4];
                    v.x -= a1.x * rn1 + a2.x * rn2 + a3.x * rn3 + a4.x * rn4;
                    v.y -= a1.y * rn1 + a2.y * rn2 + a3.y * rn3 + a4.y * rn4;
                    v.z -= a1.z * rn1 + a2.z * rn2 + a3.z * rn3 + a4.z * rn4;
                    v.w -= a1.w * rn1 + a2.w * rn2 + a3.w * rn3 + a4.w * rn4;
                    *(float4*)&augT[j][i4] = v;
                }
                augT[j][p1] = rn1 - f2e[p1] * rn2 - f3e[p1] * rn3 - f4e[p1] * rn4;
                augT[j][p2] = rn2 - f3e[p2] * rn3 - f4e[p2] * rn4;
                augT[j][p3] = rn3 - f4e[p3] * rn4;
                augT[j][p4] = rn4;
            }
        }
        __syncthreads();
    }

    for (int idx = tid; idx < M_ * M_; idx += 128) {
        int kk = idx >> 6, c = idx & 63;
        float v = augT[64 + c][pivk[kk]];
        g_S[(size_t)b * 4096 + idx] = v;
        __nv_bfloat16 h = __float2bfloat16(v);
        g_Whi[(size_t)b * 8192 + (size_t)(64 + kk) * 64 + c] = h;
        g_Wlo[(size_t)b * 8192 + (size_t)(64 + kk) * 64 + c] =
            __float2bfloat16(v - __bfloat162float(h));
    }
}

// ---------------- fused 64x64x64 x2: Tmp = S@C (smem), M = Tmp@S -> W rows 0..63 ----------------
#define MMLDS (M_ * 65)
#define MMSMEM ((MMLDS * 2 + M_ * M_) * 4)
__global__ void __launch_bounds__(256) k_mm64_fused() {
    extern __shared__ float sm[];
    float* sS = sm;
    float* sT = sm + MMLDS;
    float* sC = sm + MMLDS * 2;
    int b = blockIdx.x, tid = threadIdx.x;
    const float* S = g_S + (size_t)b * 4096;
    const float* C = g_C + (size_t)b * 4096;
    for (int i = tid; i < 4096; i += 256) {
        int r = i >> 6, c = i & 63;
        sS[r * 65 + c] = S[i];
        sC[i] = C[i];
    }
    __syncthreads();
    int tx = tid & 15, ty = tid >> 4;
    {
        float acc[4][4] = {};
        #pragma unroll 4
        for (int k = 0; k < M_; k++) {
            float xm[4], yn[4];
            #pragma unroll
            for (int i = 0; i < 4; i++) xm[i] = sS[(ty * 4 + i) * 65 + k];
            #pragma unroll
            for (int jj = 0; jj < 4; jj++) yn[jj] = sC[k * 64 + tx * 4 + jj];
            #pragma unroll
            for (int i = 0; i < 4; i++)
                #pragma unroll
                for (int jj = 0; jj < 4; jj++) acc[i][jj] += xm[i] * yn[jj];
        }
        #pragma unroll
        for (int i = 0; i < 4; i++)
            #pragma unroll
            for (int jj = 0; jj < 4; jj++)
                sT[(ty * 4 + i) * 65 + tx * 4 + jj] = acc[i][jj];
    }
    __syncthreads();
    {
        float acc[4][4] = {};
        #pragma unroll 4
        for (int k = 0; k < M_; k++) {
            float xm[4], yn[4];
            #pragma unroll
            for (int i = 0; i < 4; i++) xm[i] = sT[(ty * 4 + i) * 65 + k];
            #pragma unroll
            for (int jj = 0; jj < 4; jj++) yn[jj] = sS[k * 65 + tx * 4 + jj];
            #pragma unroll
            for (int i = 0; i < 4; i++)
                #pragma unroll
                for (int jj = 0; jj < 4; jj++) acc[i][jj] += xm[i] * yn[jj];
        }
        #pragma unroll
        for (int i = 0; i < 4; i++)
            #pragma unroll
            for (int jj = 0; jj < 4; jj++) {
                int r = ty * 4 + i, c = tx * 4 + jj;
                float v = acc[i][jj];
                __nv_bfloat16 h = __float2bfloat16(v);
                g_Whi[(size_t)b * 8192 + (size_t)r * 64 + c] = h;
                g_Wlo[(size_t)b * 8192 + (size_t)r * 64 + c] =
                    __float2bfloat16(v - __bfloat162float(h));
            }
    }
}

// ---------------- quadratic forms via mma.sync bf16 split, 4x2 warp tiling ----------------
#define QNC 128
#define QLD 72
#define QOFF_WHI   0
#define QOFF_WLO   (QOFF_WHI + 128 * QLD * 2)
#define QOFF_BHI   (QOFF_WLO + 128 * QLD * 2)
#define QOFF_BLO   (QOFF_BHI + QNC * QLD * 2)
#define QOFF_SPART (QOFF_BLO + QNC * QLD * 2)
#define QSMEM_TOTAL (QOFF_SPART + 4 * QNC * 4)

__device__ __forceinline__ void mma16816(float d[4], const uint32_t a[4], const uint32_t b[2]) {
    asm volatile(
        "mma.sync.aligned.m16n8k16.row.col.f32.bf16.bf16.f32 "
        "{%0,%1,%2,%3}, {%4,%5,%6,%7}, {%8,%9}, {%0,%1,%2,%3};"
        : "+f"(d[0]), "+f"(d[1]), "+f"(d[2]), "+f"(d[3])
        : "r"(a[0]), "r"(a[1]), "r"(a[2]), "r"(a[3]), "r"(b[0]), "r"(b[1]));
}

__global__ void __launch_bounds__(256) k_quad_mma(const float* __restrict__ A) {
    extern __shared__ char smem[];
    __nv_bfloat16* sWhi = (__nv_bfloat16*)(smem + QOFF_WHI);
    __nv_bfloat16* sWlo = (__nv_bfloat16*)(smem + QOFF_WLO);
    __nv_bfloat16* sBhi = (__nv_bfloat16*)(smem + QOFF_BHI);
    __nv_bfloat16* sBlo = (__nv_bfloat16*)(smem + QOFF_BLO);
    float* spart = (float*)(smem + QOFF_SPART);

    int tid = threadIdx.x;
    int wid = tid >> 5, lane = tid & 31;
    int wm = wid & 3;
    int wn = wid >> 2;
    int g0 = blockIdx.x * QNC;
    int b  = blockIdx.y;

    {
        const uint4* srcH = (const uint4*)(g_Whi + (size_t)b * 8192);
        const uint4* srcL = (const uint4*)(g_Wlo + (size_t)b * 8192);
        for (int i = tid; i < 1024; i += 256) {
            int r = i >> 3, c = i & 7;
            *(uint4*)&sWhi[r * QLD + c * 8] = srcH[i];
            *(uint4*)&sWlo[r * QLD + c * 8] = srcL[i];
        }
    }
    for (int i = tid; i < M_ * QNC; i += 256) {
        int k = i >> 7, g = i & (QNC - 1);
        float x = A[(size_t)k * G_ + g0 + g];
        __nv_bfloat16 h = __float2bfloat16(x);
        sBhi[g * QLD + k] = h;
        sBlo[g * QLD + k] = __float2bfloat16(x - __bfloat162float(h));
    }
    __syncthreads();

    int lr = lane >> 2;
    int cq = (lane & 3) * 2;

    float d[2][8][4];
    #pragma unroll
    for (int f = 0; f < 2; f++)
        #pragma unroll
        for (int t = 0; t < 8; t++)
            #pragma unroll
            for (int q = 0; q < 4; q++) d[f][t][q] = 0.0f;

    #pragma unroll
    for (int sp = 0; sp < 3; sp++) {
        const __nv_bfloat16* Wsrc = (sp == 2) ? sWlo : sWhi;
        const __nv_bfloat16* Bsrc = (sp == 1) ? sBlo : sBhi;
        #pragma unroll
        for (int ks = 0; ks < 4; ks++) {
            int kb = ks * 16;
            uint32_t a[2][4];
            #pragma unroll
            for (int f = 0; f < 2; f++) {
                int r0 = wm * 32 + f * 16 + lr;
                a[f][0] = *(const uint32_t*)&Wsrc[r0 * QLD + kb + cq];
                a[f][1] = *(const uint32_t*)&Wsrc[(r0 + 8) * QLD + kb + cq];
                a[f][2] = *(const uint32_t*)&Wsrc[r0 * QLD + kb + cq + 8];
                a[f][3] = *(const uint32_t*)&Wsrc[(r0 + 8) * QLD + kb + cq + 8];
            }
            #pragma unroll
            for (int t = 0; t < 8; t++) {
                int gl = wn * 64 + t * 8 + lr;
                uint32_t bb[2];
                bb[0] = *(const uint32_t*)&Bsrc[gl * QLD + kb + cq];
                bb[1] = *(const uint32_t*)&Bsrc[gl * QLD + kb + cq + 8];
                mma16816(d[0][t], a[0], bb);
                mma16816(d[1][t], a[1], bb);
            }
        }
    }

    #pragma unroll
    for (int t = 0; t < 8; t++) {
        int gcol = wn * 64 + t * 8 + cq;
        float p0 = 0.0f, p1 = 0.0f;
        #pragma unroll
        for (int f = 0; f < 2; f++) {
            int m0 = (wm * 32 + f * 16 + lr) & 63;
            int m8 = m0 + 8;
            float a00 = __bfloat162float(sBhi[gcol * QLD + m0]) + __bfloat162float(sBlo[gcol * QLD + m0]);
            float a10 = __bfloat162float(sBhi[gcol * QLD + m8]) + __bfloat162float(sBlo[gcol * QLD + m8]);
            float a01 = __bfloat162float(sBhi[(gcol + 1) * QLD + m0]) + __bfloat162float(sBlo[(gcol + 1) * QLD + m0]);
            float a11 = __bfloat162float(sBhi[(gcol + 1) * QLD + m8]) + __bfloat162float(sBlo[(gcol + 1) * QLD + m8]);
            p0 += d[f][t][0] * a00 + d[f][t][2] * a10;
            p1 += d[f][t][1] * a01 + d[f][t][3] * a11;
        }
        #pragma unroll
        for (int o = 4; o < 32; o <<= 1) {
            p0 += __shfl_xor_sync(0xffffffffu, p0, o);
            p1 += __shfl_xor_sync(0xffffffffu, p1, o);
        }
        if (lane < 4) {
            spart[wm * QNC + gcol] = p0;
            spart[wm * QNC + gcol + 1] = p1;
        }
    }
    __syncthreads();
    if (tid < QNC) {
        int g = tid;
        float t1 = spart[g] + spart[QNC + g];
        float t2 = spart[2 * QNC + g] + spart[3 * QNC + g];
        g_T1[(size_t)b * G_ + g0 + g] = t1;
        g_T2[(size_t)b * G_ + g0 + g] = fabsf(t2);
    }
}

// ---------------- per-gridpoint MLP ----------------
__global__ void k_mlp(const float* __restrict__ W1, const float* __restrict__ B1,
                      const float* __restrict__ W2, const float* __restrict__ B2,
                      const float* __restrict__ W3, const float* __restrict__ B3,
                      int it, int last, float* __restrict__ out) {
    int g = blockIdx.x;
    int b = threadIdx.x;
    __shared__ float sW1[96], sB1[32], sW2[1024], sB2[32], sW3[32], sB3;
    size_t gidx = (size_t)it * G_ + g;
    const float* w1 = W1 + gidx * 96;
    const float* w2 = W2 + gidx * 1024;
    if (b < 96) sW1[b] = w1[b];
    if (b < 32) {
        sB1[b] = B1[gidx * 32 + b];
        sB2[b] = B2[gidx * 32 + b];
        sW3[b] = W3[gidx * 32 + b];
    }
    if (b == 0) sB3 = B3[gidx];
    for (int i = b; i < 1024; i += 128) sW2[i] = w2[i];
    __syncthreads();

    float x0 = g_T1[(size_t)b * G_ + g];
    float x1 = g_T2[(size_t)b * G_ + g];
    float x2 = g_g[(size_t)b * G_ + g];

    float h[HID_];
    #pragma unroll
    for (int j = 0; j < HID_; j++) {
        float v = x0 * sW1[j] + x1 * sW1[32 + j] + x2 * sW1[64 + j] + sB1[j];
        h[j] = fmaxf(v, 0.0f);
    }
    float h2[HID_];
    #pragma unroll
    for (int j = 0; j < HID_; j++) h2[j] = sB2[j];
    #pragma unroll
    for (int j = 0; j < HID_; j++) {
        float hv = h[j];
        #pragma unroll
        for (int k = 0; k < HID_; k++) h2[k] += hv * sW2[j * 32 + k];
    }
    float o = sB3;
    #pragma unroll
    for (int k = 0; k < HID_; k++) o += fmaxf(h2[k], 0.0f) * sW3[k];

    if (last) out[(size_t)b * G_ + g] = o;
    else      g_g[(size_t)b * G_ + g] = o;
}

// ---------------- launch ----------------
extern "C" void kernel_launch(void* const* d_in, const int* in_sizes, int n_in,
                              void* d_out, int out_size) {
    const float* data = (const float*)d_in[0];
    const float* A    = (const float*)d_in[1];
    const float* W1   = (const float*)d_in[2];
    const float* b1   = (const float*)d_in[3];
    const float* W2   = (const float*)d_in[4];
    const float* b2   = (const float*)d_in[5];
    const float* W3   = (const float*)d_in[6];
    const float* b3   = (const float*)d_in[7];
    float* out = (float*)d_out;

    static int smem_set = 0;
    if (!smem_set) {
        cudaFuncSetAttribute(k_quad_mma, cudaFuncAttributeMaxDynamicSharedMemorySize, QSMEM_TOTAL);
        cudaFuncSetAttribute(k_mm64_fused, cudaFuncAttributeMaxDynamicSharedMemorySize, MMSMEM);
        smem_set = 1;
    }

    k_init<<<(B_ * G_ + 255) / 256, 256>>>();
    k_datacov<<<B_, 256>>>(data);
    for (int it = 0; it < 3; it++) {
        k_cov<<<dim3(B_, KSPLIT), 256>>>(A);
        k_inv<<<B_, 128>>>();
        k_mm64_fused<<<B_, 256, MMSMEM>>>();
        k_quad_mma<<<dim3(G_ / QNC, B_), 256, QSMEM_TOTAL>>>(A);
        k_mlp<<<G_, 128>>>(W1, b1, W2, b2, W3, b3, it, it == 2 ? 1 : 0, out);
    }
}

// round 12
// speedup vs baseline: 1.5285x; 1.0124x over previous
#include <cuda_runtime.h>
#include <cuda_bf16.h>
#include <cstdint>
#include <math.h>

#define B_      128
#define G_      2048
#define M_      64
#define T_      128
#define HID_    32
#define KSPLIT  4

// ================= scratch (device globals) =================
__device__ float g_C[B_ * M_ * M_];
__device__ float g_covp[KSPLIT * B_ * M_ * M_];
__device__ float g_T1[B_ * G_];
__device__ float g_T2[B_ * G_];
__device__ float g_g[B_ * G_];
// stacked W per batch: rows 0..63 = M = S C S, rows 64..127 = S; bf16 2-term split
__device__ __nv_bfloat16 g_Whi[B_ * 128 * 64];
__device__ __nv_bfloat16 g_Wlo[B_ * 128 * 64];

// ---------------- C_b = data_b data_b^T / T + init gamma (once) ----------------
__global__ void k_datacov(const float* __restrict__ data) {
    __shared__ float sh[M_][T_ + 1];
    int b = blockIdx.x;
    for (int i = threadIdx.x; i < G_; i += blockDim.x)
        g_g[(size_t)b * G_ + i] = 1.0f;
    const float* d = data + (size_t)b * M_ * T_;
    for (int i = threadIdx.x; i < M_ * T_; i += blockDim.x)
        sh[i >> 7][i & 127] = d[i];
    __syncthreads();
    for (int idx = threadIdx.x; idx < M_ * M_; idx += blockDim.x) {
        int m = idx >> 6, n = idx & 63;
        float acc = 0.f;
        #pragma unroll 8
        for (int t = 0; t < T_; t++) acc += sh[m][t] * sh[n][t];
        g_C[(size_t)b * 4096 + idx] = acc * (1.0f / (float)T_);
    }
}

// ---------------- cov partial (triangular, fp32 SIMT — known good) ----------------
__global__ void __launch_bounds__(256) k_cov(const float* __restrict__ A) {
    __shared__ float shA[M_][33];
    __shared__ float shg[32];
    int b = blockIdx.x;
    int ks = blockIdx.y;
    int tid = threadIdx.x;

    bool act = tid < 136;
    int ty = 0, tx = 0;
    if (act) {
        float ft = (sqrtf(8.0f * (float)tid + 1.0f) - 1.0f) * 0.5f;
        ty = (int)ft;
        if ((ty + 1) * (ty + 2) / 2 <= tid) ty++;
        if (ty * (ty + 1) / 2 > tid) ty--;
        tx = tid - ty * (ty + 1) / 2;
    }

    float acc[4][4] = {};
    int kbeg = ks * (G_ / KSPLIT), kend = kbeg + (G_ / KSPLIT);
    for (int k0 = kbeg; k0 < kend; k0 += 32) {
        for (int i = tid; i < M_ * 32; i += 256) {
            int r = i >> 5, c = i & 31;
            shA[r][c] = A[(size_t)r * G_ + k0 + c];
        }
        if (tid < 32) shg[tid] = g_g[(size_t)b * G_ + k0 + tid];
        __syncthreads();
        if (act) {
            #pragma unroll 4
            for (int k = 0; k < 32; k++) {
                float gv = shg[k];
                float am[4], an[4];
                #pragma unroll
                for (int i = 0; i < 4; i++) am[i] = shA[ty * 4 + i][k] * gv;
                #pragma unroll
                for (int j = 0; j < 4; j++) an[j] = shA[tx * 4 + j][k];
                #pragma unroll
                for (int i = 0; i < 4; i++)
                    #pragma unroll
                    for (int j = 0; j < 4; j++) acc[i][j] += am[i] * an[j];
            }
        }
        __syncthreads();
    }
    if (act) {
        float* dst = g_covp + ((size_t)ks * B_ + b) * 4096;
        #pragma unroll
        for (int i = 0; i < 4; i++)
            #pragma unroll
            for (int j = 0; j < 4; j++) {
                dst[(ty * 4 + i) * 64 + tx * 4 + j] = acc[i][j];
                dst[(tx * 4 + j) * 64 + ty * 4 + i] = acc[i][j];
            }
    }
}

// ---------------- fused: panel-4 GJ inverse + (Tmp=S@C, M=Tmp@S) + W emit ----------------
#define ILD 68
// smem carve (floats)
#define IM_AUGT 0
#define IM_F1   (128 * ILD)
#define IM_F2E  (IM_F1 + 64)
#define IM_F3E  (IM_F2E + 64)
#define IM_F4E  (IM_F3E + 64)
#define IM_F2R  (IM_F4E + 64)
#define IM_F3R  (IM_F2R + 64)
#define IM_SS   (IM_F3R + 64)
#define IM_SC   (IM_SS + 64 * 65)
#define IM_ST   (IM_SC + 64 * 64)
#define IMSMEM  ((IM_ST + 64 * 65) * 4)

__device__ __forceinline__ float wpick(float v0, float v1, int p) {
    float a = __shfl_sync(0xffffffffu, v0, p & 31);
    float b = __shfl_sync(0xffffffffu, v1, p & 31);
    return (p < 32) ? a : b;
}
__device__ __forceinline__ void wargmax(float e0, float e1, bool u0, bool u1,
                                        int lane, int& bi_out, float& bv_out) {
    float v0 = u0 ? fabsf(e0) : -1.0f;
    float v1 = u1 ? fabsf(e1) : -1.0f;
    int bi; float best, bv;
    if (v1 > v0) { best = v1; bi = lane + 32; bv = e1; }
    else         { best = v0; bi = lane;      bv = e0; }
    #pragma unroll
    for (int o = 16; o > 0; o >>= 1) {
        float ob = __shfl_xor_sync(0xffffffffu, best, o);
        int   oi = __shfl_xor_sync(0xffffffffu, bi, o);
        float ov = __shfl_xor_sync(0xffffffffu, bv, o);
        if (ob > best || (ob == best && oi < bi)) { best = ob; bi = oi; bv = ov; }
    }
    bi_out = bi; bv_out = bv;
}

__global__ void __launch_bounds__(256) k_inv_mm() {
    extern __shared__ float sm[];
    float* augT = sm + IM_AUGT;     // [128 col][ILD row] flat
    float* f1   = sm + IM_F1;
    float* f2e  = sm + IM_F2E;
    float* f3e  = sm + IM_F3E;
    float* f4e  = sm + IM_F4E;
    float* f2r  = sm + IM_F2R;
    float* f3r  = sm + IM_F3R;
    float* sS   = sm + IM_SS;       // [64][65]
    float* sC   = sm + IM_SC;       // [64][64]
    float* sT   = sm + IM_ST;       // [64][65]
    __shared__ int s_p[4];
    __shared__ float s_ip[4];
    __shared__ int pivk[M_];

    int b = blockIdx.x, tid = threadIdx.x;
    int wid = tid >> 5, lane = tid & 31;

    for (int idx = tid; idx < M_ * M_; idx += 256) {
        int i = idx >> 6, c = idx & 63;
        float v = g_covp[(size_t)b * 4096 + idx]
                + g_covp[(size_t)(B_ + b) * 4096 + idx]
                + g_covp[(size_t)(2 * B_ + b) * 4096 + idx]
                + g_covp[(size_t)(3 * B_ + b) * 4096 + idx];
        if (i == c) v += 0.1f;
        augT[c * ILD + i] = v;
        augT[(64 + c) * ILD + i] = (i == c) ? 1.0f : 0.0f;
        sC[idx] = g_C[(size_t)b * 4096 + idx];
    }
    __syncthreads();

    bool u0 = true, u1 = true;   // warp0-private

    for (int k = 0; k < M_; k += 4) {
        // Phase A
        if (wid == 0) {
            float c0 = augT[k * ILD + lane], c1 = augT[k * ILD + lane + 32];
            int p1; float pv1;
            wargmax(c0, c1, u0, u1, lane, p1, pv1);
            if (p1 == lane) u0 = false;
            if (p1 == lane + 32) u1 = false;
            if (lane == 0) { s_p[0] = p1; s_ip[0] = 1.0f / pv1; pivk[k] = p1; }
        } else if (wid == 1) {
            f1[lane] = augT[k * ILD + lane];
            f1[lane + 32] = augT[k * ILD + lane + 32];
        } else if (wid == 2) {
            f2r[lane] = augT[(k + 1) * ILD + lane];
            f2r[lane + 32] = augT[(k + 1) * ILD + lane + 32];
        } else if (wid == 3) {
            f3r[lane] = augT[(k + 2) * ILD + lane];
            f3r[lane + 32] = augT[(k + 2) * ILD + lane + 32];
        }
        __syncthreads();

        // Phase B (warp0)
        if (wid == 0) {
            int p1 = s_p[0]; float ip1 = s_ip[0];
            float f1_0 = f1[lane], f1_1 = f1[lane + 32];

            float g0 = f2r[lane], g1 = f2r[lane + 32];
            float rn12 = wpick(g0, g1, p1) * ip1;
            float e2_0 = g0 - f1_0 * rn12;
            float e2_1 = g1 - f1_1 * rn12;
            if (lane == p1)      e2_0 = rn12;
            if (lane + 32 == p1) e2_1 = rn12;
            int p2; float pv2;
            wargmax(e2_0, e2_1, u0, u1, lane, p2, pv2);
            if (p2 == lane) u0 = false;
            if (p2 == lane + 32) u1 = false;
            float ip2 = 1.0f / pv2;
            f2e[lane] = e2_0; f2e[lane + 32] = e2_1;

            float h0 = f3r[lane], h1 = f3r[lane + 32];
            float rn13 = wpick(h0, h1, p1) * ip1;
            float rn23 = (wpick(h0, h1, p2) - wpick(f1_0, f1_1, p2) * rn13) * ip2;
            float e3_0 = h0 - f1_0 * rn13 - e2_0 * rn23;
            float e3_1 = h1 - f1_1 * rn13 - e2_1 * rn23;
            if (lane == p1)      e3_0 = rn13 - e2_0 * rn23;
            if (lane + 32 == p1) e3_1 = rn13 - e2_1 * rn23;
            if (lane == p2)      e3_0 = rn23;
            if (lane + 32 == p2) e3_1 = rn23;
            int p3; float pv3;
            wargmax(e3_0, e3_1, u0, u1, lane, p3, pv3);
            if (p3 == lane) u0 = false;
            if (p3 == lane + 32) u1 = false;
            float ip3 = 1.0f / pv3;
            f3e[lane] = e3_0; f3e[lane + 32] = e3_1;

            float q0 = augT[(k + 3) * ILD + lane], q1 = augT[(k + 3) * ILD + lane + 32];
            float rn14 = wpick(q0, q1, p1) * ip1;
            float rn24 = (wpick(q0, q1, p2) - wpick(f1_0, f1_1, p2) * rn14) * ip2;
            float rn34 = (wpick(q0, q1, p3) - wpick(f1_0, f1_1, p3) * rn14
                          - wpick(e2_0, e2_1, p3) * rn24) * ip3;
            float e4_0 = q0 - f1_0 * rn14 - e2_0 * rn24 - e3_0 * rn34;
            float e4_1 = q1 - f1_1 * rn14 - e2_1 * rn24 - e3_1 * rn34;
            if (lane == p1)      e4_0 = rn14 - e2_0 * rn24 - e3_0 * rn34;
            if (lane + 32 == p1) e4_1 = rn14 - e2_1 * rn24 - e3_1 * rn34;
            if (lane == p2)      e4_0 = rn24 - e3_0 * rn34;
            if (lane + 32 == p2) e4_1 = rn24 - e3_1 * rn34;
            if (lane == p3)      e4_0 = rn34;
            if (lane + 32 == p3) e4_1 = rn34;
            int p4; float pv4;
            wargmax(e4_0, e4_1, u0, u1, lane, p4, pv4);
            if (p4 == lane) u0 = false;
            if (p4 == lane + 32) u1 = false;
            f4e[lane] = e4_0; f4e[lane + 32] = e4_1;

            if (lane == 0) {
                s_p[1] = p2; s_ip[1] = ip2; pivk[k + 1] = p2;
                s_p[2] = p3; s_ip[2] = ip3; pivk[k + 2] = p3;
                s_p[3] = p4; s_ip[3] = 1.0f / pv4; pivk[k + 3] = p4;
            }
        }
        __syncthreads();

        // Phase C: rank-4 update, 2 threads per column (warps 0-3: rows 0-31; 4-7: rows 32-63)
        {
            int jj = tid & 127;
            int half = tid >> 7;
            int rb = half * 32;
            int p1 = s_p[0], p2 = s_p[1], p3 = s_p[2], p4 = s_p[3];
            float ip1 = s_ip[0], ip2 = s_ip[1], ip3 = s_ip[2], ip4 = s_ip[3];
            float* col = augT + jj * ILD;
            float rn1 = col[p1] * ip1;
            float rn2 = (col[p2] - f1[p2] * rn1) * ip2;
            float rn3 = (col[p3] - f1[p3] * rn1 - f2e[p3] * rn2) * ip3;
            float rn4 = (col[p4] - f1[p4] * rn1 - f2e[p4] * rn2 - f3e[p4] * rn3) * ip4;
            if (rn1 != 0.0f || rn2 != 0.0f || rn3 != 0.0f || rn4 != 0.0f) {
                #pragma unroll
                for (int i4 = rb; i4 < rb + 32; i4 += 4) {
                    float4 a1 = *(const float4*)&f1[i4];
                    float4 a2 = *(const float4*)&f2e[i4];
                    float4 a3 = *(const float4*)&f3e[i4];
                    float4 a4 = *(const float4*)&f4e[i4];
                    float4 v  = *(const float4*)&col[i4];
                    v.x -= a1.x * rn1 + a2.x * rn2 + a3.x * rn3 + a4.x * rn4;
                    v.y -= a1.y * rn1 + a2.y * rn2 + a3.y * rn3 + a4.y * rn4;
                    v.z -= a1.z * rn1 + a2.z * rn2 + a3.z * rn3 + a4.z * rn4;
                    v.w -= a1.w * rn1 + a2.w * rn2 + a3.w * rn3 + a4.w * rn4;
                    *(float4*)&col[i4] = v;
                }
                if ((p1 >> 5) == half)
                    col[p1] = rn1 - f2e[p1] * rn2 - f3e[p1] * rn3 - f4e[p1] * rn4;
                if ((p2 >> 5) == half)
                    col[p2] = rn2 - f3e[p2] * rn3 - f4e[p2] * rn4;
                if ((p3 >> 5) == half)
                    col[p3] = rn3 - f4e[p3] * rn4;
                if ((p4 >> 5) == half)
                    col[p4] = rn4;
            }
        }
        __syncthreads();
    }

    // extract: sS[k][c] = Sinv[k][c]; emit bf16 split rows 64..127 of W
    for (int idx = tid; idx < M_ * M_; idx += 256) {
        int kk = idx >> 6, c = idx & 63;
        float v = augT[(64 + c) * ILD + pivk[kk]];
        sS[kk * 65 + c] = v;
        __nv_bfloat16 h = __float2bfloat16(v);
        g_Whi[(size_t)b * 8192 + (size_t)(64 + kk) * 64 + c] = h;
        g_Wlo[(size_t)b * 8192 + (size_t)(64 + kk) * 64 + c] =
            __float2bfloat16(v - __bfloat162float(h));
    }
    __syncthreads();

    // GEMM1: T = S @ C  (identical arithmetic to prior k_mm64_fused)
    int tx = tid & 15, ty = tid >> 4;
    {
        float acc[4][4] = {};
        #pragma unroll 4
        for (int k = 0; k < M_; k++) {
            float xm[4], yn[4];
            #pragma unroll
            for (int i = 0; i < 4; i++) xm[i] = sS[(ty * 4 + i) * 65 + k];
            #pragma unroll
            for (int jj = 0; jj < 4; jj++) yn[jj] = sC[k * 64 + tx * 4 + jj];
            #pragma unroll
            for (int i = 0; i < 4; i++)
                #pragma unroll
                for (int jj = 0; jj < 4; jj++) acc[i][jj] += xm[i] * yn[jj];
        }
        #pragma unroll
        for (int i = 0; i < 4; i++)
            #pragma unroll
            for (int jj = 0; jj < 4; jj++)
                sT[(ty * 4 + i) * 65 + tx * 4 + jj] = acc[i][jj];
    }
    __syncthreads();
    // GEMM2: M = T @ S -> bf16 split W rows 0..63
    {
        float acc[4][4] = {};
        #pragma unroll 4
        for (int k = 0; k < M_; k++) {
            float xm[4], yn[4];
            #pragma unroll
            for (int i = 0; i < 4; i++) xm[i] = sT[(ty * 4 + i) * 65 + k];
            #pragma unroll
            for (int jj = 0; jj < 4; jj++) yn[jj] = sS[k * 65 + tx * 4 + jj];
            #pragma unroll
            for (int i = 0; i < 4; i++)
                #pragma unroll
                for (int jj = 0; jj < 4; jj++) acc[i][jj] += xm[i] * yn[jj];
        }
        #pragma unroll
        for (int i = 0; i < 4; i++)
            #pragma unroll
            for (int jj = 0; jj < 4; jj++) {
                int r = ty * 4 + i, c = tx * 4 + jj;
                float v = acc[i][jj];
                __nv_bfloat16 h = __float2bfloat16(v);
                g_Whi[(size_t)b * 8192 + (size_t)r * 64 + c] = h;
                g_Wlo[(size_t)b * 8192 + (size_t)r * 64 + c] =
                    __float2bfloat16(v - __bfloat162float(h));
            }
    }
}

// ---------------- quadratic forms via mma.sync bf16 split, 4x2 warp tiling ----------------
#define QNC 128
#define QLD 72
#define QOFF_WHI   0
#define QOFF_WLO   (QOFF_WHI + 128 * QLD * 2)
#define QOFF_BHI   (QOFF_WLO + 128 * QLD * 2)
#define QOFF_BLO   (QOFF_BHI + QNC * QLD * 2)
#define QOFF_SPART (QOFF_BLO + QNC * QLD * 2)
#define QSMEM_TOTAL (QOFF_SPART + 4 * QNC * 4)

__device__ __forceinline__ void mma16816(float d[4], const uint32_t a[4], const uint32_t b[2]) {
    asm volatile(
        "mma.sync.aligned.m16n8k16.row.col.f32.bf16.bf16.f32 "
        "{%0,%1,%2,%3}, {%4,%5,%6,%7}, {%8,%9}, {%0,%1,%2,%3};"
        : "+f"(d[0]), "+f"(d[1]), "+f"(d[2]), "+f"(d[3])
        : "r"(a[0]), "r"(a[1]), "r"(a[2]), "r"(a[3]), "r"(b[0]), "r"(b[1]));
}

__global__ void __launch_bounds__(256) k_quad_mma(const float* __restrict__ A) {
    extern __shared__ char smem[];
    __nv_bfloat16* sWhi = (__nv_bfloat16*)(smem + QOFF_WHI);
    __nv_bfloat16* sWlo = (__nv_bfloat16*)(smem + QOFF_WLO);
    __nv_bfloat16* sBhi = (__nv_bfloat16*)(smem + QOFF_BHI);
    __nv_bfloat16* sBlo = (__nv_bfloat16*)(smem + QOFF_BLO);
    float* spart = (float*)(smem + QOFF_SPART);

    int tid = threadIdx.x;
    int wid = tid >> 5, lane = tid & 31;
    int wm = wid & 3;
    int wn = wid >> 2;
    int g0 = blockIdx.x * QNC;
    int b  = blockIdx.y;

    {
        const uint4* srcH = (const uint4*)(g_Whi + (size_t)b * 8192);
        const uint4* srcL = (const uint4*)(g_Wlo + (size_t)b * 8192);
        for (int i = tid; i < 1024; i += 256) {
            int r = i >> 3, c = i & 7;
            *(uint4*)&sWhi[r * QLD + c * 8] = srcH[i];
            *(uint4*)&sWlo[r * QLD + c * 8] = srcL[i];
        }
    }
    for (int i = tid; i < M_ * QNC; i += 256) {
        int k = i >> 7, g = i & (QNC - 1);
        float x = A[(size_t)k * G_ + g0 + g];
        __nv_bfloat16 h = __float2bfloat16(x);
        sBhi[g * QLD + k] = h;
        sBlo[g * QLD + k] = __float2bfloat16(x - __bfloat162float(h));
    }
    __syncthreads();

    int lr = lane >> 2;
    int cq = (lane & 3) * 2;

    float d[2][8][4];
    #pragma unroll
    for (int f = 0; f < 2; f++)
        #pragma unroll
        for (int t = 0; t < 8; t++)
            #pragma unroll
            for (int q = 0; q < 4; q++) d[f][t][q] = 0.0f;

    #pragma unroll
    for (int sp = 0; sp < 3; sp++) {
        const __nv_bfloat16* Wsrc = (sp == 2) ? sWlo : sWhi;
        const __nv_bfloat16* Bsrc = (sp == 1) ? sBlo : sBhi;
        #pragma unroll
        for (int ks = 0; ks < 4; ks++) {
            int kb = ks * 16;
            uint32_t a[2][4];
            #pragma unroll
            for (int f = 0; f < 2; f++) {
                int r0 = wm * 32 + f * 16 + lr;
                a[f][0] = *(const uint32_t*)&Wsrc[r0 * QLD + kb + cq];
                a[f][1] = *(const uint32_t*)&Wsrc[(r0 + 8) * QLD + kb + cq];
                a[f][2] = *(const uint32_t*)&Wsrc[r0 * QLD + kb + cq + 8];
                a[f][3] = *(const uint32_t*)&Wsrc[(r0 + 8) * QLD + kb + cq + 8];
            }
            #pragma unroll
            for (int t = 0; t < 8; t++) {
                int gl = wn * 64 + t * 8 + lr;
                uint32_t bb[2];
                bb[0] = *(const uint32_t*)&Bsrc[gl * QLD + kb + cq];
                bb[1] = *(const uint32_t*)&Bsrc[gl * QLD + kb + cq + 8];
                mma16816(d[0][t], a[0], bb);
                mma16816(d[1][t], a[1], bb);
            }
        }
    }

    #pragma unroll
    for (int t = 0; t < 8; t++) {
        int gcol = wn * 64 + t * 8 + cq;
        float p0 = 0.0f, p1 = 0.0f;
        #pragma unroll
        for (int f = 0; f < 2; f++) {
            int m0 = (wm * 32 + f * 16 + lr) & 63;
            int m8 = m0 + 8;
            float a00 = __bfloat162float(sBhi[gcol * QLD + m0]) + __bfloat162float(sBlo[gcol * QLD + m0]);
            float a10 = __bfloat162float(sBhi[gcol * QLD + m8]) + __bfloat162float(sBlo[gcol * QLD + m8]);
            float a01 = __bfloat162float(sBhi[(gcol + 1) * QLD + m0]) + __bfloat162float(sBlo[(gcol + 1) * QLD + m0]);
            float a11 = __bfloat162float(sBhi[(gcol + 1) * QLD + m8]) + __bfloat162float(sBlo[(gcol + 1) * QLD + m8]);
            p0 += d[f][t][0] * a00 + d[f][t][2] * a10;
            p1 += d[f][t][1] * a01 + d[f][t][3] * a11;
        }
        #pragma unroll
        for (int o = 4; o < 32; o <<= 1) {
            p0 += __shfl_xor_sync(0xffffffffu, p0, o);
            p1 += __shfl_xor_sync(0xffffffffu, p1, o);
        }
        if (lane < 4) {
            spart[wm * QNC + gcol] = p0;
            spart[wm * QNC + gcol + 1] = p1;
        }
    }
    __syncthreads();
    if (tid < QNC) {
        int g = tid;
        float t1 = spart[g] + spart[QNC + g];
        float t2 = spart[2 * QNC + g] + spart[3 * QNC + g];
        g_T1[(size_t)b * G_ + g0 + g] = t1;
        g_T2[(size_t)b * G_ + g0 + g] = fabsf(t2);
    }
}

// ---------------- per-gridpoint MLP ----------------
__global__ void k_mlp(const float* __restrict__ W1, const float* __restrict__ B1,
                      const float* __restrict__ W2, const float* __restrict__ B2,
                      const float* __restrict__ W3, const float* __restrict__ B3,
                      int it, int last, float* __restrict__ out) {
    int g = blockIdx.x;
    int b = threadIdx.x;
    __shared__ float sW1[96], sB1[32], sW2[1024], sB2[32], sW3[32], sB3;
    size_t gidx = (size_t)it * G_ + g;
    const float* w1 = W1 + gidx * 96;
    const float* w2 = W2 + gidx * 1024;
    if (b < 96) sW1[b] = w1[b];
    if (b < 32) {
        sB1[b] = B1[gidx * 32 + b];
        sB2[b] = B2[gidx * 32 + b];
        sW3[b] = W3[gidx * 32 + b];
    }
    if (b == 0) sB3 = B3[gidx];
    for (int i = b; i < 1024; i += 128) sW2[i] = w2[i];
    __syncthreads();

    float x0 = g_T1[(size_t)b * G_ + g];
    float x1 = g_T2[(size_t)b * G_ + g];
    float x2 = g_g[(size_t)b * G_ + g];

    float h[HID_];
    #pragma unroll
    for (int j = 0; j < HID_; j++) {
        float v = x0 * sW1[j] + x1 * sW1[32 + j] + x2 * sW1[64 + j] + sB1[j];
        h[j] = fmaxf(v, 0.0f);
    }
    float h2[HID_];
    #pragma unroll
    for (int j = 0; j < HID_; j++) h2[j] = sB2[j];
    #pragma unroll
    for (int j = 0; j < HID_; j++) {
        float hv = h[j];
        #pragma unroll
        for (int k = 0; k < HID_; k++) h2[k] += hv * sW2[j * 32 + k];
    }
    float o = sB3;
    #pragma unroll
    for (int k = 0; k < HID_; k++) o += fmaxf(h2[k], 0.0f) * sW3[k];

    if (last) out[(size_t)b * G_ + g] = o;
    else      g_g[(size_t)b * G_ + g] = o;
}

// ---------------- launch ----------------
extern "C" void kernel_launch(void* const* d_in, const int* in_sizes, int n_in,
                              void* d_out, int out_size) {
    const float* data = (const float*)d_in[0];
    const float* A    = (const float*)d_in[1];
    const float* W1   = (const float*)d_in[2];
    const float* b1   = (const float*)d_in[3];
    const float* W2   = (const float*)d_in[4];
    const float* b2   = (const float*)d_in[5];
    const float* W3   = (const float*)d_in[6];
    const float* b3   = (const float*)d_in[7];
    float* out = (float*)d_out;

    static int smem_set = 0;
    if (!smem_set) {
        cudaFuncSetAttribute(k_quad_mma, cudaFuncAttributeMaxDynamicSharedMemorySize, QSMEM_TOTAL);
        cudaFuncSetAttribute(k_inv_mm, cudaFuncAttributeMaxDynamicSharedMemorySize, IMSMEM);
        smem_set = 1;
    }

    k_datacov<<<B_, 256>>>(data);
    for (int it = 0; it < 3; it++) {
        k_cov<<<dim3(B_, KSPLIT), 256>>>(A);
        k_inv_mm<<<B_, 256, IMSMEM>>>();
        k_quad_mma<<<dim3(G_ / QNC, B_), 256, QSMEM_TOTAL>>>(A);
        k_mlp<<<G_, 128>>>(W1, b1, W2, b2, W3, b3, it, it == 2 ? 1 : 0, out);
    }
}